// round 4
// baseline (speedup 1.0000x reference)
#include <cuda_runtime.h>
#include <math.h>

#define NNODES 100000
#define NEDGES 3200000
#define F 256

// Scratch (allocation-free contract: __device__ globals)
__device__ float g_h[(size_t)NNODES * F];   // 102.4 MB
__device__ float g_q[NNODES];
__device__ float g_k[NNODES];
__device__ float g_m[NNODES];
__device__ float g_s[NNODES];
__device__ float g_c[NEDGES];               // 12.8 MB

// ---------------------------------------------------------------------------
// K0: init m = -inf, s = 0
// ---------------------------------------------------------------------------
__global__ void init_ms_kernel(int n) {
    int i = blockIdx.x * blockDim.x + threadIdx.x;
    if (i < n) { g_m[i] = -INFINITY; g_s[i] = 0.0f; }
}

// ---------------------------------------------------------------------------
// K1: h = x @ Wv + bv   (M x 256) = (M x 256)(256 x 256)
// Classic 128x128 tile, BK=8, 256 threads, 8x8 per thread, float4 I/O.
// ---------------------------------------------------------------------------
__global__ __launch_bounds__(256) void gemm_kernel(
    const float* __restrict__ A,   // x  [M,256]
    const float* __restrict__ B,   // Wv [256,256]
    const float* __restrict__ bias,
    int M)
{
    __shared__ float As[8][128];
    __shared__ float Bs[8][128];

    const int t    = threadIdx.x;
    const int brow = blockIdx.y;
    const int bcol = blockIdx.x;
    const int tr   = t >> 4;       // 0..15
    const int tc   = t & 15;       // 0..15

    // A-tile loader: 128 rows x 8 cols; thread loads one float4
    const int irA = t >> 1;
    const int icA = (t & 1) * 4;
    // B-tile loader: 8 rows x 128 cols; thread loads one float4
    const int irB = t >> 5;
    const int icB = (t & 31) * 4;

    int arow = brow * 128 + irA;
    if (arow >= M) arow = M - 1;            // clamp reads; stores guarded
    const float* aptr = A + (size_t)arow * 256 + icA;
    const float* bptr = B + (size_t)irB * 256 + bcol * 128 + icB;

    float acc[8][8];
    #pragma unroll
    for (int i = 0; i < 8; i++)
        #pragma unroll
        for (int j = 0; j < 8; j++) acc[i][j] = 0.0f;

    for (int k0 = 0; k0 < 256; k0 += 8) {
        float4 a4 = *(const float4*)(aptr + k0);
        float4 b4 = *(const float4*)(bptr + (size_t)k0 * 256);
        As[icA + 0][irA] = a4.x;
        As[icA + 1][irA] = a4.y;
        As[icA + 2][irA] = a4.z;
        As[icA + 3][irA] = a4.w;
        *(float4*)&Bs[irB][icB] = b4;
        __syncthreads();

        #pragma unroll
        for (int kk = 0; kk < 8; kk++) {
            float ra[8], rb[8];
            #pragma unroll
            for (int i = 0; i < 8; i++) ra[i] = As[kk][tr * 8 + i];
            #pragma unroll
            for (int j = 0; j < 8; j++) rb[j] = Bs[kk][tc * 8 + j];
            #pragma unroll
            for (int i = 0; i < 8; i++)
                #pragma unroll
                for (int j = 0; j < 8; j++) acc[i][j] += ra[i] * rb[j];
        }
        __syncthreads();
    }

    const int colBase = bcol * 128 + tc * 8;
    float bv0[8];
    #pragma unroll
    for (int j = 0; j < 8; j++) bv0[j] = bias[colBase + j];

    #pragma unroll
    for (int i = 0; i < 8; i++) {
        int row = brow * 128 + tr * 8 + i;
        if (row < M) {
            float* orow = g_h + (size_t)row * 256 + colBase;
            float4 o0 = make_float4(acc[i][0] + bv0[0], acc[i][1] + bv0[1],
                                    acc[i][2] + bv0[2], acc[i][3] + bv0[3]);
            float4 o1 = make_float4(acc[i][4] + bv0[4], acc[i][5] + bv0[5],
                                    acc[i][6] + bv0[6], acc[i][7] + bv0[7]);
            *(float4*)(orow + 0) = o0;
            *(float4*)(orow + 4) = o1;
        }
    }
}

// ---------------------------------------------------------------------------
// K2: q = h@wq + bq, k = h@wk + bk  — one warp per node
// ---------------------------------------------------------------------------
__global__ __launch_bounds__(256) void qk_kernel(
    const float* __restrict__ wq, const float* __restrict__ bq,
    const float* __restrict__ wk, const float* __restrict__ bk, int n)
{
    int warp = (blockIdx.x * blockDim.x + threadIdx.x) >> 5;
    int lane = threadIdx.x & 31;
    if (warp >= n) return;

    const float4* hrow = (const float4*)(g_h + (size_t)warp * F);
    const float4* q4 = (const float4*)wq;
    const float4* k4 = (const float4*)wk;

    float sq = 0.f, sk = 0.f;
    #pragma unroll
    for (int it = 0; it < 2; it++) {
        int idx = lane + it * 32;
        float4 hv = hrow[idx];
        float4 qv = q4[idx];
        float4 kv = k4[idx];
        sq += hv.x * qv.x + hv.y * qv.y + hv.z * qv.z + hv.w * qv.w;
        sk += hv.x * kv.x + hv.y * kv.y + hv.z * kv.z + hv.w * kv.w;
    }
    #pragma unroll
    for (int o = 16; o; o >>= 1) {
        sq += __shfl_xor_sync(0xFFFFFFFFu, sq, o);
        sk += __shfl_xor_sync(0xFFFFFFFFu, sk, o);
    }
    if (lane == 0) {
        g_q[warp] = sq + bq[0];
        g_k[warp] = sk + bk[0];
    }
}

// ---------------------------------------------------------------------------
// K3: c = leakyrelu(q[src]+k[dst]); segment max into m[dst]
// float atomic max via sign trick (m initialized to -inf)
// ---------------------------------------------------------------------------
__global__ __launch_bounds__(256) void edge_logits_kernel(
    const int* __restrict__ src, const int* __restrict__ dst, int E)
{
    int e = blockIdx.x * blockDim.x + threadIdx.x;
    if (e >= E) return;
    int s_ = src[e], d_ = dst[e];
    float v = g_q[s_] + g_k[d_];
    float c = v > 0.f ? v : 0.2f * v;
    g_c[e] = c;
    if (c >= 0.f)
        atomicMax((int*)&g_m[d_], __float_as_int(c));
    else
        atomicMin((unsigned int*)&g_m[d_], (unsigned int)__float_as_int(c));
}

// ---------------------------------------------------------------------------
// K4: s[dst] += exp(c - m[dst])
// ---------------------------------------------------------------------------
__global__ __launch_bounds__(256) void edge_expsum_kernel(
    const int* __restrict__ dst, int E)
{
    int e = blockIdx.x * blockDim.x + threadIdx.x;
    if (e >= E) return;
    int d_ = dst[e];
    atomicAdd(&g_s[d_], __expf(g_c[e] - g_m[d_]));
}

// ---------------------------------------------------------------------------
// K5: out[dst] += attn * h[src]   — one warp per edge, red.add.v4.f32
// ---------------------------------------------------------------------------
__device__ __forceinline__ void red_add_v4(float* addr, float4 v) {
    asm volatile("red.global.add.v4.f32 [%0], {%1,%2,%3,%4};"
                 :: "l"(addr), "f"(v.x), "f"(v.y), "f"(v.z), "f"(v.w)
                 : "memory");
}

__global__ __launch_bounds__(256) void scatter_kernel(
    const int* __restrict__ src, const int* __restrict__ dst,
    float* __restrict__ out, int E)
{
    int e = blockIdx.x * 8 + (threadIdx.x >> 5);
    int lane = threadIdx.x & 31;
    if (e >= E) return;
    int s_ = src[e], d_ = dst[e];
    float attn = __expf(g_c[e] - g_m[d_]) / g_s[d_];

    const float4* hrow = (const float4*)(g_h + (size_t)s_ * F);
    float* orow = out + (size_t)d_ * F;

    float4 h0 = hrow[lane];
    float4 h1 = hrow[lane + 32];
    red_add_v4(orow + lane * 4,
               make_float4(h0.x * attn, h0.y * attn, h0.z * attn, h0.w * attn));
    red_add_v4(orow + 128 + lane * 4,
               make_float4(h1.x * attn, h1.y * attn, h1.z * attn, h1.w * attn));
}

// ---------------------------------------------------------------------------
extern "C" void kernel_launch(void* const* d_in, const int* in_sizes, int n_in,
                              void* d_out, int out_size)
{
    const float* x  = (const float*)d_in[0];
    const float* Wv = (const float*)d_in[1];
    const float* bv = (const float*)d_in[2];
    const float* wq = (const float*)d_in[3];
    const float* bq = (const float*)d_in[4];
    const float* wk = (const float*)d_in[5];
    const float* bk = (const float*)d_in[6];
    const int*   src = (const int*)d_in[7];
    const int*   dst = (const int*)d_in[8];

    const int M = in_sizes[0] / F;      // 100000
    const int E = in_sizes[7];          // 3200000

    cudaMemsetAsync(d_out, 0, (size_t)out_size * sizeof(float));
    init_ms_kernel<<<(M + 255) / 256, 256>>>(M);

    dim3 ggrid(2, (M + 127) / 128);
    gemm_kernel<<<ggrid, 256>>>(x, Wv, bv, M);

    qk_kernel<<<(M + 7) / 8, 256>>>(wq, bq, wk, bk, M);
    edge_logits_kernel<<<(E + 255) / 256, 256>>>(src, dst, E);
    edge_expsum_kernel<<<(E + 255) / 256, 256>>>(dst, E);
    scatter_kernel<<<(E + 7) / 8, 256>>>(src, dst, (float*)d_out, E);
}

// round 5
// speedup vs baseline: 1.0001x; 1.0001x over previous
#include <cuda_runtime.h>
#include <math.h>

#define NNODES 100000
#define NEDGES 3200000
#define F 256

// Scratch (allocation-free contract: __device__ globals)
__device__ float g_h[(size_t)NNODES * F];   // 102.4 MB
__device__ float g_q[NNODES];
__device__ float g_k[NNODES];
__device__ float g_m[NNODES];
__device__ float g_s[NNODES];
__device__ float g_c[NEDGES];               // 12.8 MB

// ---------------------------------------------------------------------------
// K0: init m = -inf, s = 0
// ---------------------------------------------------------------------------
__global__ void init_ms_kernel(int n) {
    int i = blockIdx.x * blockDim.x + threadIdx.x;
    if (i < n) { g_m[i] = -INFINITY; g_s[i] = 0.0f; }
}

// ---------------------------------------------------------------------------
// K1: h = x @ Wv + bv   (M x 256) = (M x 256)(256 x 256)
// Classic 128x128 tile, BK=8, 256 threads, 8x8 per thread, float4 I/O.
// ---------------------------------------------------------------------------
__global__ __launch_bounds__(256) void gemm_kernel(
    const float* __restrict__ A,   // x  [M,256]
    const float* __restrict__ B,   // Wv [256,256]
    const float* __restrict__ bias,
    int M)
{
    __shared__ float As[8][128];
    __shared__ float Bs[8][128];

    const int t    = threadIdx.x;
    const int brow = blockIdx.y;
    const int bcol = blockIdx.x;
    const int tr   = t >> 4;       // 0..15
    const int tc   = t & 15;       // 0..15

    // A-tile loader: 128 rows x 8 cols; thread loads one float4
    const int irA = t >> 1;
    const int icA = (t & 1) * 4;
    // B-tile loader: 8 rows x 128 cols; thread loads one float4
    const int irB = t >> 5;
    const int icB = (t & 31) * 4;

    int arow = brow * 128 + irA;
    if (arow >= M) arow = M - 1;            // clamp reads; stores guarded
    const float* aptr = A + (size_t)arow * 256 + icA;
    const float* bptr = B + (size_t)irB * 256 + bcol * 128 + icB;

    float acc[8][8];
    #pragma unroll
    for (int i = 0; i < 8; i++)
        #pragma unroll
        for (int j = 0; j < 8; j++) acc[i][j] = 0.0f;

    for (int k0 = 0; k0 < 256; k0 += 8) {
        float4 a4 = *(const float4*)(aptr + k0);
        float4 b4 = *(const float4*)(bptr + (size_t)k0 * 256);
        As[icA + 0][irA] = a4.x;
        As[icA + 1][irA] = a4.y;
        As[icA + 2][irA] = a4.z;
        As[icA + 3][irA] = a4.w;
        *(float4*)&Bs[irB][icB] = b4;
        __syncthreads();

        #pragma unroll
        for (int kk = 0; kk < 8; kk++) {
            float ra[8], rb[8];
            #pragma unroll
            for (int i = 0; i < 8; i++) ra[i] = As[kk][tr * 8 + i];
            #pragma unroll
            for (int j = 0; j < 8; j++) rb[j] = Bs[kk][tc * 8 + j];
            #pragma unroll
            for (int i = 0; i < 8; i++)
                #pragma unroll
                for (int j = 0; j < 8; j++) acc[i][j] += ra[i] * rb[j];
        }
        __syncthreads();
    }

    const int colBase = bcol * 128 + tc * 8;
    float bv0[8];
    #pragma unroll
    for (int j = 0; j < 8; j++) bv0[j] = bias[colBase + j];

    #pragma unroll
    for (int i = 0; i < 8; i++) {
        int row = brow * 128 + tr * 8 + i;
        if (row < M) {
            float* orow = g_h + (size_t)row * 256 + colBase;
            float4 o0 = make_float4(acc[i][0] + bv0[0], acc[i][1] + bv0[1],
                                    acc[i][2] + bv0[2], acc[i][3] + bv0[3]);
            float4 o1 = make_float4(acc[i][4] + bv0[4], acc[i][5] + bv0[5],
                                    acc[i][6] + bv0[6], acc[i][7] + bv0[7]);
            *(float4*)(orow + 0) = o0;
            *(float4*)(orow + 4) = o1;
        }
    }
}

// ---------------------------------------------------------------------------
// K2: q = h@wq + bq, k = h@wk + bk  — one warp per node
// ---------------------------------------------------------------------------
__global__ __launch_bounds__(256) void qk_kernel(
    const float* __restrict__ wq, const float* __restrict__ bq,
    const float* __restrict__ wk, const float* __restrict__ bk, int n)
{
    int warp = (blockIdx.x * blockDim.x + threadIdx.x) >> 5;
    int lane = threadIdx.x & 31;
    if (warp >= n) return;

    const float4* hrow = (const float4*)(g_h + (size_t)warp * F);
    const float4* q4 = (const float4*)wq;
    const float4* k4 = (const float4*)wk;

    float sq = 0.f, sk = 0.f;
    #pragma unroll
    for (int it = 0; it < 2; it++) {
        int idx = lane + it * 32;
        float4 hv = hrow[idx];
        float4 qv = q4[idx];
        float4 kv = k4[idx];
        sq += hv.x * qv.x + hv.y * qv.y + hv.z * qv.z + hv.w * qv.w;
        sk += hv.x * kv.x + hv.y * kv.y + hv.z * kv.z + hv.w * kv.w;
    }
    #pragma unroll
    for (int o = 16; o; o >>= 1) {
        sq += __shfl_xor_sync(0xFFFFFFFFu, sq, o);
        sk += __shfl_xor_sync(0xFFFFFFFFu, sk, o);
    }
    if (lane == 0) {
        g_q[warp] = sq + bq[0];
        g_k[warp] = sk + bk[0];
    }
}

// ---------------------------------------------------------------------------
// K3: c = leakyrelu(q[src]+k[dst]); segment max into m[dst]
// float atomic max via sign trick (m initialized to -inf)
// ---------------------------------------------------------------------------
__global__ __launch_bounds__(256) void edge_logits_kernel(
    const int* __restrict__ src, const int* __restrict__ dst, int E)
{
    int e = blockIdx.x * blockDim.x + threadIdx.x;
    if (e >= E) return;
    int s_ = src[e], d_ = dst[e];
    float v = g_q[s_] + g_k[d_];
    float c = v > 0.f ? v : 0.2f * v;
    g_c[e] = c;
    if (c >= 0.f)
        atomicMax((int*)&g_m[d_], __float_as_int(c));
    else
        atomicMin((unsigned int*)&g_m[d_], (unsigned int)__float_as_int(c));
}

// ---------------------------------------------------------------------------
// K4: s[dst] += exp(c - m[dst])
// ---------------------------------------------------------------------------
__global__ __launch_bounds__(256) void edge_expsum_kernel(
    const int* __restrict__ dst, int E)
{
    int e = blockIdx.x * blockDim.x + threadIdx.x;
    if (e >= E) return;
    int d_ = dst[e];
    atomicAdd(&g_s[d_], __expf(g_c[e] - g_m[d_]));
}

// ---------------------------------------------------------------------------
// K5: out[dst] += attn * h[src]   — one warp per edge, red.add.v4.f32
// ---------------------------------------------------------------------------
__device__ __forceinline__ void red_add_v4(float* addr, float4 v) {
    asm volatile("red.global.add.v4.f32 [%0], {%1,%2,%3,%4};"
                 :: "l"(addr), "f"(v.x), "f"(v.y), "f"(v.z), "f"(v.w)
                 : "memory");
}

__global__ __launch_bounds__(256) void scatter_kernel(
    const int* __restrict__ src, const int* __restrict__ dst,
    float* __restrict__ out, int E)
{
    int e = blockIdx.x * 8 + (threadIdx.x >> 5);
    int lane = threadIdx.x & 31;
    if (e >= E) return;
    int s_ = src[e], d_ = dst[e];
    float attn = __expf(g_c[e] - g_m[d_]) / g_s[d_];

    const float4* hrow = (const float4*)(g_h + (size_t)s_ * F);
    float* orow = out + (size_t)d_ * F;

    float4 h0 = hrow[lane];
    float4 h1 = hrow[lane + 32];
    red_add_v4(orow + lane * 4,
               make_float4(h0.x * attn, h0.y * attn, h0.z * attn, h0.w * attn));
    red_add_v4(orow + 128 + lane * 4,
               make_float4(h1.x * attn, h1.y * attn, h1.z * attn, h1.w * attn));
}

// ---------------------------------------------------------------------------
extern "C" void kernel_launch(void* const* d_in, const int* in_sizes, int n_in,
                              void* d_out, int out_size)
{
    const float* x  = (const float*)d_in[0];
    const float* Wv = (const float*)d_in[1];
    const float* bv = (const float*)d_in[2];
    const float* wq = (const float*)d_in[3];
    const float* bq = (const float*)d_in[4];
    const float* wk = (const float*)d_in[5];
    const float* bk = (const float*)d_in[6];
    const int*   src = (const int*)d_in[7];
    const int*   dst = (const int*)d_in[8];

    const int M = in_sizes[0] / F;      // 100000
    const int E = in_sizes[7];          // 3200000

    cudaMemsetAsync(d_out, 0, (size_t)out_size * sizeof(float));
    init_ms_kernel<<<(M + 255) / 256, 256>>>(M);

    dim3 ggrid(2, (M + 127) / 128);
    gemm_kernel<<<ggrid, 256>>>(x, Wv, bv, M);

    qk_kernel<<<(M + 7) / 8, 256>>>(wq, bq, wk, bk, M);
    edge_logits_kernel<<<(E + 255) / 256, 256>>>(src, dst, E);
    edge_expsum_kernel<<<(E + 255) / 256, 256>>>(dst, E);
    scatter_kernel<<<(E + 7) / 8, 256>>>(src, dst, (float*)d_out, E);
}

// round 6
// speedup vs baseline: 1.5667x; 1.5666x over previous
#include <cuda_runtime.h>
#include <math.h>

#define NNODES 100000
#define NEDGES 3200000
#define F 256

// Scratch (allocation-free contract: __device__ globals)
__device__ float g_h[(size_t)NNODES * F];   // 102.4 MB
__device__ float g_q[NNODES];
__device__ float g_k[NNODES];
__device__ int   g_cnt[NNODES];             // histogram, then bucket cursor
__device__ int   g_off[NNODES + 1];         // CSR offsets by dst
__device__ int   g_src_sorted[NEDGES];      // src node per dst-sorted edge

// ---------------------------------------------------------------------------
// K0: zero the histogram
// ---------------------------------------------------------------------------
__global__ void init_cnt_kernel(int n) {
    int i = blockIdx.x * blockDim.x + threadIdx.x;
    if (i < n) g_cnt[i] = 0;
}

// ---------------------------------------------------------------------------
// K1: h = x @ Wv + bv   (M x 256) = (M x 256)(256 x 256)
// Classic 128x128 tile, BK=8, 256 threads, 8x8 per thread, float4 I/O.
// ---------------------------------------------------------------------------
__global__ __launch_bounds__(256) void gemm_kernel(
    const float* __restrict__ A,   // x  [M,256]
    const float* __restrict__ B,   // Wv [256,256]
    const float* __restrict__ bias,
    int M)
{
    __shared__ float As[8][128];
    __shared__ float Bs[8][128];

    const int t    = threadIdx.x;
    const int brow = blockIdx.y;
    const int bcol = blockIdx.x;
    const int tr   = t >> 4;       // 0..15
    const int tc   = t & 15;       // 0..15

    const int irA = t >> 1;
    const int icA = (t & 1) * 4;
    const int irB = t >> 5;
    const int icB = (t & 31) * 4;

    int arow = brow * 128 + irA;
    if (arow >= M) arow = M - 1;            // clamp reads; stores guarded
    const float* aptr = A + (size_t)arow * 256 + icA;
    const float* bptr = B + (size_t)irB * 256 + bcol * 128 + icB;

    float acc[8][8];
    #pragma unroll
    for (int i = 0; i < 8; i++)
        #pragma unroll
        for (int j = 0; j < 8; j++) acc[i][j] = 0.0f;

    for (int k0 = 0; k0 < 256; k0 += 8) {
        float4 a4 = *(const float4*)(aptr + k0);
        float4 b4 = *(const float4*)(bptr + (size_t)k0 * 256);
        As[icA + 0][irA] = a4.x;
        As[icA + 1][irA] = a4.y;
        As[icA + 2][irA] = a4.z;
        As[icA + 3][irA] = a4.w;
        *(float4*)&Bs[irB][icB] = b4;
        __syncthreads();

        #pragma unroll
        for (int kk = 0; kk < 8; kk++) {
            float ra[8], rb[8];
            #pragma unroll
            for (int i = 0; i < 8; i++) ra[i] = As[kk][tr * 8 + i];
            #pragma unroll
            for (int j = 0; j < 8; j++) rb[j] = Bs[kk][tc * 8 + j];
            #pragma unroll
            for (int i = 0; i < 8; i++)
                #pragma unroll
                for (int j = 0; j < 8; j++) acc[i][j] += ra[i] * rb[j];
        }
        __syncthreads();
    }

    const int colBase = bcol * 128 + tc * 8;
    float bv0[8];
    #pragma unroll
    for (int j = 0; j < 8; j++) bv0[j] = bias[colBase + j];

    #pragma unroll
    for (int i = 0; i < 8; i++) {
        int row = brow * 128 + tr * 8 + i;
        if (row < M) {
            float* orow = g_h + (size_t)row * 256 + colBase;
            float4 o0 = make_float4(acc[i][0] + bv0[0], acc[i][1] + bv0[1],
                                    acc[i][2] + bv0[2], acc[i][3] + bv0[3]);
            float4 o1 = make_float4(acc[i][4] + bv0[4], acc[i][5] + bv0[5],
                                    acc[i][6] + bv0[6], acc[i][7] + bv0[7]);
            *(float4*)(orow + 0) = o0;
            *(float4*)(orow + 4) = o1;
        }
    }
}

// ---------------------------------------------------------------------------
// K2: q = h@wq + bq, k = h@wk + bk  — one warp per node
// ---------------------------------------------------------------------------
__global__ __launch_bounds__(256) void qk_kernel(
    const float* __restrict__ wq, const float* __restrict__ bq,
    const float* __restrict__ wk, const float* __restrict__ bk, int n)
{
    int warp = (blockIdx.x * blockDim.x + threadIdx.x) >> 5;
    int lane = threadIdx.x & 31;
    if (warp >= n) return;

    const float4* hrow = (const float4*)(g_h + (size_t)warp * F);
    const float4* q4 = (const float4*)wq;
    const float4* k4 = (const float4*)wk;

    float sq = 0.f, sk = 0.f;
    #pragma unroll
    for (int it = 0; it < 2; it++) {
        int idx = lane + it * 32;
        float4 hv = hrow[idx];
        float4 qv = q4[idx];
        float4 kv = k4[idx];
        sq += hv.x * qv.x + hv.y * qv.y + hv.z * qv.z + hv.w * qv.w;
        sk += hv.x * kv.x + hv.y * kv.y + hv.z * kv.z + hv.w * kv.w;
    }
    #pragma unroll
    for (int o = 16; o; o >>= 1) {
        sq += __shfl_xor_sync(0xFFFFFFFFu, sq, o);
        sk += __shfl_xor_sync(0xFFFFFFFFu, sk, o);
    }
    if (lane == 0) {
        g_q[warp] = sq + bq[0];
        g_k[warp] = sk + bk[0];
    }
}

// ---------------------------------------------------------------------------
// K3: histogram of dst
// ---------------------------------------------------------------------------
__global__ __launch_bounds__(256) void hist_kernel(
    const int* __restrict__ dst, int E)
{
    int e = blockIdx.x * blockDim.x + threadIdx.x;
    if (e < E) atomicAdd(&g_cnt[dst[e]], 1);
}

// ---------------------------------------------------------------------------
// K4: single-block exclusive scan of g_cnt -> g_off; g_cnt becomes cursor
// ---------------------------------------------------------------------------
__global__ __launch_bounds__(1024) void scan_kernel(int n, int E) {
    __shared__ int ssum[1024];
    const int t = threadIdx.x;
    const int chunk = (n + 1023) / 1024;
    const int beg = t * chunk;
    const int end = min(beg + chunk, n);

    int sum = 0;
    for (int i = beg; i < end; i++) sum += g_cnt[i];
    ssum[t] = sum;
    __syncthreads();

    // Hillis-Steele inclusive scan over thread sums
    #pragma unroll
    for (int o = 1; o < 1024; o <<= 1) {
        int v = (t >= o) ? ssum[t - o] : 0;
        __syncthreads();
        ssum[t] += v;
        __syncthreads();
    }

    int run = (t == 0) ? 0 : ssum[t - 1];
    for (int i = beg; i < end; i++) {
        int c = g_cnt[i];
        g_off[i] = run;
        g_cnt[i] = run;      // cursor for bucket scatter
        run += c;
    }
    if (end == n) g_off[n] = E;
}

// ---------------------------------------------------------------------------
// K5: bucket-scatter src indices into dst-sorted order
// ---------------------------------------------------------------------------
__global__ __launch_bounds__(256) void bucket_kernel(
    const int* __restrict__ src, const int* __restrict__ dst, int E)
{
    int e = blockIdx.x * blockDim.x + threadIdx.x;
    if (e >= E) return;
    int pos = atomicAdd(&g_cnt[dst[e]], 1);
    g_src_sorted[pos] = src[e];
}

// ---------------------------------------------------------------------------
// K6: fused per-dst-segment softmax + weighted aggregation.
// One warp per dst node. Pass 1: warp-strided online softmax (m, s).
// Pass 2: serial over segment edges, warp-cooperative over 256 features,
// register accumulation, single store of the output row (no atomics).
// ---------------------------------------------------------------------------
__global__ __launch_bounds__(256) void gat_segment_kernel(
    float* __restrict__ out, int n)
{
    int d    = (blockIdx.x * blockDim.x + threadIdx.x) >> 5;
    int lane = threadIdx.x & 31;
    if (d >= n) return;

    const int beg = g_off[d];
    const int end = g_off[d + 1];
    float4* orow = (float4*)(out + (size_t)d * F);

    if (beg == end) {
        float4 z = make_float4(0.f, 0.f, 0.f, 0.f);
        orow[lane]      = z;
        orow[lane + 32] = z;
        return;
    }

    const float kd = g_k[d];

    // Pass 1: online softmax statistics, lanes stride over segment
    float m = -INFINITY, s = 0.f;
    for (int i = beg + lane; i < end; i += 32) {
        float v = g_q[g_src_sorted[i]] + kd;
        float c = v > 0.f ? v : 0.2f * v;
        if (c > m) { s *= __expf(m - c); m = c; }
        s += __expf(c - m);
    }
    // warp combine of (m, s) pairs — safe for empty lanes (m=-inf, s=0)
    #pragma unroll
    for (int o = 16; o; o >>= 1) {
        float mo = __shfl_xor_sync(0xFFFFFFFFu, m, o);
        float so = __shfl_xor_sync(0xFFFFFFFFu, s, o);
        if (mo > m)       { s = s * __expf(m - mo) + so; m = mo; }
        else if (mo == m) { s += so; }
        else              { s += so * __expf(mo - m); }
    }
    const float inv_s = 1.0f / s;

    // Pass 2: serial over edges, all lanes cooperate on the feature dim
    float4 a0 = make_float4(0.f, 0.f, 0.f, 0.f);
    float4 a1 = make_float4(0.f, 0.f, 0.f, 0.f);
    for (int i = beg; i < end; ++i) {
        int sidx = g_src_sorted[i];                 // broadcast load
        float v  = g_q[sidx] + kd;                  // broadcast load
        float c  = v > 0.f ? v : 0.2f * v;
        float w  = __expf(c - m) * inv_s;
        const float4* hrow = (const float4*)(g_h + (size_t)sidx * F);
        float4 h0 = hrow[lane];
        float4 h1 = hrow[lane + 32];
        a0.x = fmaf(w, h0.x, a0.x); a0.y = fmaf(w, h0.y, a0.y);
        a0.z = fmaf(w, h0.z, a0.z); a0.w = fmaf(w, h0.w, a0.w);
        a1.x = fmaf(w, h1.x, a1.x); a1.y = fmaf(w, h1.y, a1.y);
        a1.z = fmaf(w, h1.z, a1.z); a1.w = fmaf(w, h1.w, a1.w);
    }
    orow[lane]      = a0;
    orow[lane + 32] = a1;
}

// ---------------------------------------------------------------------------
extern "C" void kernel_launch(void* const* d_in, const int* in_sizes, int n_in,
                              void* d_out, int out_size)
{
    const float* x  = (const float*)d_in[0];
    const float* Wv = (const float*)d_in[1];
    const float* bv = (const float*)d_in[2];
    const float* wq = (const float*)d_in[3];
    const float* bq = (const float*)d_in[4];
    const float* wk = (const float*)d_in[5];
    const float* bk = (const float*)d_in[6];
    const int*   src = (const int*)d_in[7];
    const int*   dst = (const int*)d_in[8];

    const int M = in_sizes[0] / F;      // 100000
    const int E = in_sizes[7];          // 3200000

    init_cnt_kernel<<<(M + 255) / 256, 256>>>(M);

    dim3 ggrid(2, (M + 127) / 128);
    gemm_kernel<<<ggrid, 256>>>(x, Wv, bv, M);

    qk_kernel<<<(M + 7) / 8, 256>>>(wq, bq, wk, bk, M);

    hist_kernel<<<(E + 255) / 256, 256>>>(dst, E);
    scan_kernel<<<1, 1024>>>(M, E);
    bucket_kernel<<<(E + 255) / 256, 256>>>(src, dst, E);

    gat_segment_kernel<<<(M * 32 + 255) / 256, 256>>>((float*)d_out, M);
}

// round 7
// speedup vs baseline: 1.7897x; 1.1423x over previous
#include <cuda_runtime.h>
#include <cuda_fp16.h>
#include <math.h>

#define NNODES 100000
#define NEDGES 3200000
#define F 256

// Scratch (allocation-free contract: __device__ globals)
__device__ __half g_hh[(size_t)NNODES * F]; // 51.2 MB (L2-resident)
__device__ float g_q[NNODES];
__device__ float g_k[NNODES];
__device__ int   g_cnt[NNODES];             // histogram, then bucket cursor
__device__ int   g_off[NNODES + 1];         // CSR offsets by dst
__device__ int   g_src_sorted[NEDGES];      // src node per dst-sorted edge

// ---------------------------------------------------------------------------
// K0: zero histogram; init q/k accumulators with their biases
// ---------------------------------------------------------------------------
__global__ void init_kernel(const float* __restrict__ bq,
                            const float* __restrict__ bk, int n) {
    int i = blockIdx.x * blockDim.x + threadIdx.x;
    if (i < n) { g_cnt[i] = 0; g_q[i] = bq[0]; g_k[i] = bk[0]; }
}

// ---------------------------------------------------------------------------
// K1: h = x @ Wv + bv, stored fp16. Epilogue also computes exact fp32
//     q = h@wq, k = h@wk partials (deterministic: half-warp shuffle tree +
//     exactly 2 commutative atomicAdd contributors per row).
// ---------------------------------------------------------------------------
__global__ __launch_bounds__(256) void gemm_kernel(
    const float* __restrict__ A,   // x  [M,256]
    const float* __restrict__ B,   // Wv [256,256]
    const float* __restrict__ bias,
    const float* __restrict__ wq,
    const float* __restrict__ wk,
    int M)
{
    __shared__ float As[8][128];
    __shared__ float Bs[8][128];

    const int t    = threadIdx.x;
    const int brow = blockIdx.y;
    const int bcol = blockIdx.x;
    const int tr   = t >> 4;       // 0..15
    const int tc   = t & 15;       // 0..15

    const int irA = t >> 1;
    const int icA = (t & 1) * 4;
    const int irB = t >> 5;
    const int icB = (t & 31) * 4;

    int arow = brow * 128 + irA;
    if (arow >= M) arow = M - 1;            // clamp reads; stores guarded
    const float* aptr = A + (size_t)arow * 256 + icA;
    const float* bptr = B + (size_t)irB * 256 + bcol * 128 + icB;

    float acc[8][8];
    #pragma unroll
    for (int i = 0; i < 8; i++)
        #pragma unroll
        for (int j = 0; j < 8; j++) acc[i][j] = 0.0f;

    for (int k0 = 0; k0 < 256; k0 += 8) {
        float4 a4 = *(const float4*)(aptr + k0);
        float4 b4 = *(const float4*)(bptr + (size_t)k0 * 256);
        As[icA + 0][irA] = a4.x;
        As[icA + 1][irA] = a4.y;
        As[icA + 2][irA] = a4.z;
        As[icA + 3][irA] = a4.w;
        *(float4*)&Bs[irB][icB] = b4;
        __syncthreads();

        #pragma unroll
        for (int kk = 0; kk < 8; kk++) {
            float ra[8], rb[8];
            #pragma unroll
            for (int i = 0; i < 8; i++) ra[i] = As[kk][tr * 8 + i];
            #pragma unroll
            for (int j = 0; j < 8; j++) rb[j] = Bs[kk][tc * 8 + j];
            #pragma unroll
            for (int i = 0; i < 8; i++)
                #pragma unroll
                for (int j = 0; j < 8; j++) acc[i][j] += ra[i] * rb[j];
        }
        __syncthreads();
    }

    const int colBase = bcol * 128 + tc * 8;
    float bv0[8], wq0[8], wk0[8];
    #pragma unroll
    for (int j = 0; j < 8; j++) {
        bv0[j] = bias[colBase + j];
        wq0[j] = wq[colBase + j];
        wk0[j] = wk[colBase + j];
    }

    #pragma unroll
    for (int i = 0; i < 8; i++) {
        const int row = brow * 128 + tr * 8 + i;
        float hv[8];
        #pragma unroll
        for (int j = 0; j < 8; j++) hv[j] = acc[i][j] + bv0[j];

        // fp16 store of this row-slice (8 halves = 16B)
        if (row < M) {
            __half2 hp[4];
            #pragma unroll
            for (int j = 0; j < 4; j++)
                hp[j] = __float22half2_rn(make_float2(hv[2 * j], hv[2 * j + 1]));
            *(uint4*)(g_hh + (size_t)row * F + colBase) = *(uint4*)hp;
        }

        // exact fp32 q/k partials
        float pq = 0.f, pk = 0.f;
        #pragma unroll
        for (int j = 0; j < 8; j++) {
            pq = fmaf(hv[j], wq0[j], pq);
            pk = fmaf(hv[j], wk0[j], pk);
        }
        // reduce across the 16 threads (tc) sharing this row: contiguous
        // 16-lane group within a warp -> xor shuffles 1,2,4,8
        #pragma unroll
        for (int o = 1; o < 16; o <<= 1) {
            pq += __shfl_xor_sync(0xFFFFFFFFu, pq, o);
            pk += __shfl_xor_sync(0xFFFFFFFFu, pk, o);
        }
        if (tc == 0 && row < M) {
            atomicAdd(&g_q[row], pq);   // 2 contributors (bcol 0/1): commutative
            atomicAdd(&g_k[row], pk);
        }
    }
}

// ---------------------------------------------------------------------------
// K2: histogram of dst
// ---------------------------------------------------------------------------
__global__ __launch_bounds__(256) void hist_kernel(
    const int* __restrict__ dst, int E)
{
    int e = blockIdx.x * blockDim.x + threadIdx.x;
    if (e < E) atomicAdd(&g_cnt[dst[e]], 1);
}

// ---------------------------------------------------------------------------
// K3: single-block exclusive scan of g_cnt -> g_off; g_cnt becomes cursor
// ---------------------------------------------------------------------------
__global__ __launch_bounds__(1024) void scan_kernel(int n, int E) {
    __shared__ int ssum[1024];
    const int t = threadIdx.x;
    const int chunk = (n + 1023) / 1024;
    const int beg = t * chunk;
    const int end = min(beg + chunk, n);

    int sum = 0;
    for (int i = beg; i < end; i++) sum += g_cnt[i];
    ssum[t] = sum;
    __syncthreads();

    #pragma unroll
    for (int o = 1; o < 1024; o <<= 1) {
        int v = (t >= o) ? ssum[t - o] : 0;
        __syncthreads();
        ssum[t] += v;
        __syncthreads();
    }

    int run = (t == 0) ? 0 : ssum[t - 1];
    for (int i = beg; i < end; i++) {
        int c = g_cnt[i];
        g_off[i] = run;
        g_cnt[i] = run;      // cursor for bucket scatter
        run += c;
    }
    if (end == n) g_off[n] = E;
}

// ---------------------------------------------------------------------------
// K4: bucket-scatter src indices into dst-sorted order
// ---------------------------------------------------------------------------
__global__ __launch_bounds__(256) void bucket_kernel(
    const int* __restrict__ src, const int* __restrict__ dst, int E)
{
    int e = blockIdx.x * blockDim.x + threadIdx.x;
    if (e >= E) return;
    int pos = atomicAdd(&g_cnt[dst[e]], 1);
    g_src_sorted[pos] = src[e];
}

// ---------------------------------------------------------------------------
// K5: fused per-dst-segment softmax + weighted aggregation.
// One warp per dst node. Pass 1: warp-strided online softmax (m, s).
// Pass 2: serial over segment edges, warp-cooperative over 256 features,
// fp16 gather (16B/lane/edge), fp32 register accumulation, single store.
// ---------------------------------------------------------------------------
__global__ __launch_bounds__(256) void gat_segment_kernel(
    float* __restrict__ out, int n)
{
    int d    = (blockIdx.x * blockDim.x + threadIdx.x) >> 5;
    int lane = threadIdx.x & 31;
    if (d >= n) return;

    const int beg = g_off[d];
    const int end = g_off[d + 1];
    float4* orow = (float4*)(out + (size_t)d * F);

    if (beg == end) {
        float4 z = make_float4(0.f, 0.f, 0.f, 0.f);
        orow[lane * 2]     = z;
        orow[lane * 2 + 1] = z;
        return;
    }

    const float kd = g_k[d];

    // Pass 1: online softmax statistics, lanes stride over segment
    float m = -INFINITY, s = 0.f;
    for (int i = beg + lane; i < end; i += 32) {
        float v = g_q[g_src_sorted[i]] + kd;
        float c = v > 0.f ? v : 0.2f * v;
        if (c > m) { s *= __expf(m - c); m = c; }
        s += __expf(c - m);
    }
    #pragma unroll
    for (int o = 16; o; o >>= 1) {
        float mo = __shfl_xor_sync(0xFFFFFFFFu, m, o);
        float so = __shfl_xor_sync(0xFFFFFFFFu, s, o);
        if (mo > m)       { s = s * __expf(m - mo) + so; m = mo; }
        else if (mo == m) { s += so; }
        else              { s += so * __expf(mo - m); }
    }
    const float inv_s = 1.0f / s;

    // Pass 2: serial over edges, lanes cooperate on the feature dim.
    // lane covers cols [lane*8, lane*8+8): one 16B fp16 load per edge.
    float a[8];
    #pragma unroll
    for (int j = 0; j < 8; j++) a[j] = 0.f;

    for (int i = beg; i < end; ++i) {
        int sidx = g_src_sorted[i];                 // broadcast load
        float v  = g_q[sidx] + kd;                  // broadcast load
        float c  = v > 0.f ? v : 0.2f * v;
        float w  = __expf(c - m) * inv_s;

        uint4 raw = *(const uint4*)(g_hh + (size_t)sidx * F + lane * 8);
        const __half2* hp = (const __half2*)&raw;
        #pragma unroll
        for (int j = 0; j < 4; j++) {
            float2 f = __half22float2(hp[j]);
            a[2 * j]     = fmaf(w, f.x, a[2 * j]);
            a[2 * j + 1] = fmaf(w, f.y, a[2 * j + 1]);
        }
    }
    orow[lane * 2]     = make_float4(a[0], a[1], a[2], a[3]);
    orow[lane * 2 + 1] = make_float4(a[4], a[5], a[6], a[7]);
}

// ---------------------------------------------------------------------------
extern "C" void kernel_launch(void* const* d_in, const int* in_sizes, int n_in,
                              void* d_out, int out_size)
{
    const float* x  = (const float*)d_in[0];
    const float* Wv = (const float*)d_in[1];
    const float* bv = (const float*)d_in[2];
    const float* wq = (const float*)d_in[3];
    const float* bq = (const float*)d_in[4];
    const float* wk = (const float*)d_in[5];
    const float* bk = (const float*)d_in[6];
    const int*   src = (const int*)d_in[7];
    const int*   dst = (const int*)d_in[8];

    const int M = in_sizes[0] / F;      // 100000
    const int E = in_sizes[7];          // 3200000

    init_kernel<<<(M + 255) / 256, 256>>>(bq, bk, M);

    dim3 ggrid(2, (M + 127) / 128);
    gemm_kernel<<<ggrid, 256>>>(x, Wv, bv, wq, wk, M);

    hist_kernel<<<(E + 255) / 256, 256>>>(dst, E);
    scan_kernel<<<1, 1024>>>(M, E);
    bucket_kernel<<<(E + 255) / 256, 256>>>(src, dst, E);

    gat_segment_kernel<<<(M * 32 + 255) / 256, 256>>>((float*)d_out, M);
}

// round 8
// speedup vs baseline: 2.2030x; 1.2309x over previous
#include <cuda_runtime.h>
#include <cuda_fp16.h>
#include <math.h>

#define NNODES 100000
#define NEDGES 3200000
#define F 256
#define SCAN_B 1024
#define NBLK ((NNODES + SCAN_B - 1) / SCAN_B)   // 98

// Scratch (allocation-free contract: __device__ globals)
__device__ __half g_hh[(size_t)NNODES * F]; // 51.2 MB (L2-resident)
__device__ float g_q[NNODES];
__device__ float g_k[NNODES];
__device__ int   g_cnt[NNODES];             // histogram, then bucket cursor
__device__ int   g_off[NNODES + 1];         // CSR offsets by dst
__device__ int   g_src_sorted[NEDGES];      // src node per dst-sorted edge
__device__ int   g_bsum[128];               // per-block partial sums

// ---------------------------------------------------------------------------
// K0: zero histogram; init q/k accumulators with their biases
// ---------------------------------------------------------------------------
__global__ void init_kernel(const float* __restrict__ bq,
                            const float* __restrict__ bk, int n) {
    int i = blockIdx.x * blockDim.x + threadIdx.x;
    if (i < n) { g_cnt[i] = 0; g_q[i] = bq[0]; g_k[i] = bk[0]; }
}

// ---------------------------------------------------------------------------
// K1: h = x @ Wv + bv, stored fp16. Epilogue also computes exact fp32
//     q = h@wq, k = h@wk partials (deterministic: half-warp shuffle tree +
//     exactly 2 commutative atomicAdd contributors per row).
// ---------------------------------------------------------------------------
__global__ __launch_bounds__(256) void gemm_kernel(
    const float* __restrict__ A,   // x  [M,256]
    const float* __restrict__ B,   // Wv [256,256]
    const float* __restrict__ bias,
    const float* __restrict__ wq,
    const float* __restrict__ wk,
    int M)
{
    __shared__ float As[8][128];
    __shared__ float Bs[8][128];

    const int t    = threadIdx.x;
    const int brow = blockIdx.y;
    const int bcol = blockIdx.x;
    const int tr   = t >> 4;       // 0..15
    const int tc   = t & 15;       // 0..15

    const int irA = t >> 1;
    const int icA = (t & 1) * 4;
    const int irB = t >> 5;
    const int icB = (t & 31) * 4;

    int arow = brow * 128 + irA;
    if (arow >= M) arow = M - 1;            // clamp reads; stores guarded
    const float* aptr = A + (size_t)arow * 256 + icA;
    const float* bptr = B + (size_t)irB * 256 + bcol * 128 + icB;

    float acc[8][8];
    #pragma unroll
    for (int i = 0; i < 8; i++)
        #pragma unroll
        for (int j = 0; j < 8; j++) acc[i][j] = 0.0f;

    for (int k0 = 0; k0 < 256; k0 += 8) {
        float4 a4 = *(const float4*)(aptr + k0);
        float4 b4 = *(const float4*)(bptr + (size_t)k0 * 256);
        As[icA + 0][irA] = a4.x;
        As[icA + 1][irA] = a4.y;
        As[icA + 2][irA] = a4.z;
        As[icA + 3][irA] = a4.w;
        *(float4*)&Bs[irB][icB] = b4;
        __syncthreads();

        #pragma unroll
        for (int kk = 0; kk < 8; kk++) {
            float ra[8], rb[8];
            #pragma unroll
            for (int i = 0; i < 8; i++) ra[i] = As[kk][tr * 8 + i];
            #pragma unroll
            for (int j = 0; j < 8; j++) rb[j] = Bs[kk][tc * 8 + j];
            #pragma unroll
            for (int i = 0; i < 8; i++)
                #pragma unroll
                for (int j = 0; j < 8; j++) acc[i][j] += ra[i] * rb[j];
        }
        __syncthreads();
    }

    const int colBase = bcol * 128 + tc * 8;
    float bv0[8], wq0[8], wk0[8];
    #pragma unroll
    for (int j = 0; j < 8; j++) {
        bv0[j] = bias[colBase + j];
        wq0[j] = wq[colBase + j];
        wk0[j] = wk[colBase + j];
    }

    #pragma unroll
    for (int i = 0; i < 8; i++) {
        const int row = brow * 128 + tr * 8 + i;
        float hv[8];
        #pragma unroll
        for (int j = 0; j < 8; j++) hv[j] = acc[i][j] + bv0[j];

        // fp16 store of this row-slice (8 halves = 16B)
        if (row < M) {
            __half2 hp[4];
            #pragma unroll
            for (int j = 0; j < 4; j++)
                hp[j] = __float22half2_rn(make_float2(hv[2 * j], hv[2 * j + 1]));
            *(uint4*)(g_hh + (size_t)row * F + colBase) = *(uint4*)hp;
        }

        // exact fp32 q/k partials
        float pq = 0.f, pk = 0.f;
        #pragma unroll
        for (int j = 0; j < 8; j++) {
            pq = fmaf(hv[j], wq0[j], pq);
            pk = fmaf(hv[j], wk0[j], pk);
        }
        // reduce across the 16 threads (tc) sharing this row
        #pragma unroll
        for (int o = 1; o < 16; o <<= 1) {
            pq += __shfl_xor_sync(0xFFFFFFFFu, pq, o);
            pk += __shfl_xor_sync(0xFFFFFFFFu, pk, o);
        }
        if (tc == 0 && row < M) {
            atomicAdd(&g_q[row], pq);   // 2 contributors (bcol 0/1): commutative
            atomicAdd(&g_k[row], pk);
        }
    }
}

// ---------------------------------------------------------------------------
// K2: histogram of dst
// ---------------------------------------------------------------------------
__global__ __launch_bounds__(256) void hist_kernel(
    const int* __restrict__ dst, int E)
{
    int e = blockIdx.x * blockDim.x + threadIdx.x;
    if (e < E) atomicAdd(&g_cnt[dst[e]], 1);
}

// ---------------------------------------------------------------------------
// K3a: per-block reduction of counts -> g_bsum
// ---------------------------------------------------------------------------
__global__ __launch_bounds__(SCAN_B) void partial_kernel(int n) {
    __shared__ int sh[SCAN_B];
    const int t = threadIdx.x;
    const int i = blockIdx.x * SCAN_B + t;
    sh[t] = (i < n) ? g_cnt[i] : 0;
    __syncthreads();
    #pragma unroll
    for (int o = SCAN_B / 2; o; o >>= 1) {
        if (t < o) sh[t] += sh[t + o];
        __syncthreads();
    }
    if (t == 0) g_bsum[blockIdx.x] = sh[0];
}

// ---------------------------------------------------------------------------
// K3b: single tiny block: exclusive scan of the 98 block sums
// ---------------------------------------------------------------------------
__global__ __launch_bounds__(128) void scanb_kernel(int nb) {
    __shared__ int sh[128];
    const int t = threadIdx.x;
    sh[t] = (t < nb) ? g_bsum[t] : 0;
    __syncthreads();
    #pragma unroll
    for (int o = 1; o < 128; o <<= 1) {
        int v = (t >= o) ? sh[t - o] : 0;
        __syncthreads();
        sh[t] += v;
        __syncthreads();
    }
    if (t < nb) g_bsum[t] = (t == 0) ? 0 : sh[t - 1];
}

// ---------------------------------------------------------------------------
// K3c: per-block exclusive scan + block prefix -> g_off, g_cnt cursor
// ---------------------------------------------------------------------------
__global__ __launch_bounds__(SCAN_B) void offsets_kernel(int n, int E) {
    __shared__ int sh[SCAN_B];
    const int t = threadIdx.x;
    const int i = blockIdx.x * SCAN_B + t;
    const int v = (i < n) ? g_cnt[i] : 0;
    sh[t] = v;
    __syncthreads();
    #pragma unroll
    for (int o = 1; o < SCAN_B; o <<= 1) {
        int u = (t >= o) ? sh[t - o] : 0;
        __syncthreads();
        sh[t] += u;
        __syncthreads();
    }
    if (i < n) {
        int excl = sh[t] - v + g_bsum[blockIdx.x];
        g_off[i] = excl;
        g_cnt[i] = excl;     // cursor for bucket scatter
        if (i == n - 1) g_off[n] = E;
    }
}

// ---------------------------------------------------------------------------
// K4: bucket-scatter src indices into dst-sorted order
// ---------------------------------------------------------------------------
__global__ __launch_bounds__(256) void bucket_kernel(
    const int* __restrict__ src, const int* __restrict__ dst, int E)
{
    int e = blockIdx.x * blockDim.x + threadIdx.x;
    if (e >= E) return;
    int pos = atomicAdd(&g_cnt[dst[e]], 1);
    g_src_sorted[pos] = src[e];
}

// ---------------------------------------------------------------------------
// K5: fused per-dst-segment softmax + weighted aggregation.
// One warp per dst node. Pass 1: warp-strided online softmax (m, s).
// Pass 2: serial over segment edges, warp-cooperative over 256 features,
// fp16 gather (16B/lane/edge), fp32 register accumulation, single store.
// ---------------------------------------------------------------------------
__global__ __launch_bounds__(256) void gat_segment_kernel(
    float* __restrict__ out, int n)
{
    int d    = (blockIdx.x * blockDim.x + threadIdx.x) >> 5;
    int lane = threadIdx.x & 31;
    if (d >= n) return;

    const int beg = g_off[d];
    const int end = g_off[d + 1];
    float4* orow = (float4*)(out + (size_t)d * F);

    if (beg == end) {
        float4 z = make_float4(0.f, 0.f, 0.f, 0.f);
        orow[lane * 2]     = z;
        orow[lane * 2 + 1] = z;
        return;
    }

    const float kd = g_k[d];

    // Pass 1: online softmax statistics, lanes stride over segment
    float m = -INFINITY, s = 0.f;
    for (int i = beg + lane; i < end; i += 32) {
        float v = g_q[g_src_sorted[i]] + kd;
        float c = v > 0.f ? v : 0.2f * v;
        if (c > m) { s *= __expf(m - c); m = c; }
        s += __expf(c - m);
    }
    #pragma unroll
    for (int o = 16; o; o >>= 1) {
        float mo = __shfl_xor_sync(0xFFFFFFFFu, m, o);
        float so = __shfl_xor_sync(0xFFFFFFFFu, s, o);
        if (mo > m)       { s = s * __expf(m - mo) + so; m = mo; }
        else if (mo == m) { s += so; }
        else              { s += so * __expf(mo - m); }
    }
    const float inv_s = 1.0f / s;

    // Pass 2: serial over edges, lanes cooperate on the feature dim.
    float a[8];
    #pragma unroll
    for (int j = 0; j < 8; j++) a[j] = 0.f;

    for (int i = beg; i < end; ++i) {
        int sidx = g_src_sorted[i];                 // broadcast load
        float v  = g_q[sidx] + kd;                  // broadcast load
        float c  = v > 0.f ? v : 0.2f * v;
        float w  = __expf(c - m) * inv_s;

        uint4 raw = *(const uint4*)(g_hh + (size_t)sidx * F + lane * 8);
        const __half2* hp = (const __half2*)&raw;
        #pragma unroll
        for (int j = 0; j < 4; j++) {
            float2 f = __half22float2(hp[j]);
            a[2 * j]     = fmaf(w, f.x, a[2 * j]);
            a[2 * j + 1] = fmaf(w, f.y, a[2 * j + 1]);
        }
    }
    orow[lane * 2]     = make_float4(a[0], a[1], a[2], a[3]);
    orow[lane * 2 + 1] = make_float4(a[4], a[5], a[6], a[7]);
}

// ---------------------------------------------------------------------------
extern "C" void kernel_launch(void* const* d_in, const int* in_sizes, int n_in,
                              void* d_out, int out_size)
{
    const float* x  = (const float*)d_in[0];
    const float* Wv = (const float*)d_in[1];
    const float* bv = (const float*)d_in[2];
    const float* wq = (const float*)d_in[3];
    const float* bq = (const float*)d_in[4];
    const float* wk = (const float*)d_in[5];
    const float* bk = (const float*)d_in[6];
    const int*   src = (const int*)d_in[7];
    const int*   dst = (const int*)d_in[8];

    const int M = in_sizes[0] / F;      // 100000
    const int E = in_sizes[7];          // 3200000
    const int nb = (M + SCAN_B - 1) / SCAN_B;

    init_kernel<<<(M + 255) / 256, 256>>>(bq, bk, M);

    dim3 ggrid(2, (M + 127) / 128);
    gemm_kernel<<<ggrid, 256>>>(x, Wv, bv, wq, wk, M);

    hist_kernel<<<(E + 255) / 256, 256>>>(dst, E);
    partial_kernel<<<nb, SCAN_B>>>(M);
    scanb_kernel<<<1, 128>>>(nb);
    offsets_kernel<<<nb, SCAN_B>>>(M, E);
    bucket_kernel<<<(E + 255) / 256, 256>>>(src, dst, E);

    gat_segment_kernel<<<(M * 32 + 255) / 256, 256>>>((float*)d_out, M);
}

// round 10
// speedup vs baseline: 3.1098x; 1.4116x over previous
#include <cuda_runtime.h>
#include <cuda_fp16.h>
#include <math.h>
#include <stdint.h>

#define NNODES 100000
#define NEDGES 3200000
#define F 256
#define SCAN_B 1024
#define MTILE 128

// Scratch (allocation-free contract: __device__ globals)
__device__ __half g_hh[(size_t)NNODES * F]; // 51.2 MB (L2-resident)
__device__ float g_q[NNODES];
__device__ float g_k[NNODES];
__device__ int   g_cnt[NNODES];             // histogram, then bucket cursor
__device__ int   g_off[NNODES + 1];         // CSR offsets by dst
__device__ int   g_src_sorted[NEDGES];      // src node per dst-sorted edge
__device__ int   g_bsum[128];               // per-block partial sums
// W pre-converted to fp16 hi/lo in [N=256][K] K-major, SW128-swizzled,
// 4 K-chunk tiles (chunk = 64 K-cols) of 16384 halves each.
__device__ __half g_Bhi[256 * 256];
__device__ __half g_Blo[256 * 256];

// ---------------------------------------------------------------------------
// helpers
// ---------------------------------------------------------------------------
__device__ __forceinline__ uint32_t smem_u32(const void* p) {
    uint32_t a;
    asm("{ .reg .u64 t; cvta.to.shared.u64 t, %1; cvt.u32.u64 %0, t; }"
        : "=r"(a) : "l"(p));
    return a;
}
#define SWZ128(o) ((o) ^ (((o) >> 3) & 0x70))

__device__ __forceinline__ void ldsm4(uint32_t* r, uint32_t addr) {
    asm volatile("ldmatrix.sync.aligned.m8n8.x4.shared.b16 {%0,%1,%2,%3}, [%4];"
        : "=r"(r[0]), "=r"(r[1]), "=r"(r[2]), "=r"(r[3]) : "r"(addr));
}
__device__ __forceinline__ void mma16816(float* d, const uint32_t* a,
                                         const uint32_t* b) {
    asm volatile(
        "mma.sync.aligned.m16n8k16.row.col.f32.f16.f16.f32 "
        "{%0,%1,%2,%3}, {%4,%5,%6,%7}, {%8,%9}, {%0,%1,%2,%3};"
        : "+f"(d[0]), "+f"(d[1]), "+f"(d[2]), "+f"(d[3])
        : "r"(a[0]), "r"(a[1]), "r"(a[2]), "r"(a[3]), "r"(b[0]), "r"(b[1]));
}

// ---------------------------------------------------------------------------
// SMEM layout (dynamic)
// ---------------------------------------------------------------------------
#define S_WQ    0                       // 256 floats
#define S_WK    1024
#define S_BIAS  2048
#define S_AHI   4096                    // 128 x 64 fp16 = 16 KB (SW128)
#define S_ALO   (S_AHI + 16384)
#define S_BHI   (S_ALO + 16384)         // 256 x 64 fp16 = 32 KB (SW128)
#define S_BLO   (S_BHI + 32768)
#define S_TOTAL (S_BLO + 32768)         // 102400 B

// ---------------------------------------------------------------------------
// K0: zero histogram; init q/k accumulators with biases
// ---------------------------------------------------------------------------
__global__ void init_kernel(const float* __restrict__ bq,
                            const float* __restrict__ bk, int n) {
    int i = blockIdx.x * blockDim.x + threadIdx.x;
    if (i < n) { g_cnt[i] = 0; g_q[i] = bq[0]; g_k[i] = bk[0]; }
}

// ---------------------------------------------------------------------------
// K0b: convert Wv [K=256][N=256] fp32 -> g_Bhi/g_Blo [N][K] fp16 hi/lo,
//      SW128-swizzled, 4 chunk tiles (chunk = 64 K-cols).
// ---------------------------------------------------------------------------
__global__ __launch_bounds__(256) void convw_kernel(const float* __restrict__ W) {
    int idx = blockIdx.x * blockDim.x + threadIdx.x;   // 0..65535
    int kk = idx & 63;          // K within chunk
    int n  = (idx >> 6) & 255;  // N row
    int c  = idx >> 14;         // chunk
    int k  = c * 64 + kk;
    float v = W[k * 256 + n];
    __half hi = __float2half_rn(v);
    __half lo = __float2half_rn(v - __half2float(hi));
    uint32_t off = SWZ128((uint32_t)(n * 128 + kk * 2));
    uint32_t gidx = (uint32_t)c * 16384u + (off >> 1);
    g_Bhi[gidx] = hi;
    g_Blo[gidx] = lo;
}

// ---------------------------------------------------------------------------
// K1: HMMA GEMM: h = x @ Wv + bv (fp16-split, fp32 accum),
//     epilogue writes g_hh (fp16) + exact q/k partials (4-way atomicAdd).
// 256 threads = 8 warps, warp grid 2x4, warp tile 64x64.
// ---------------------------------------------------------------------------
__global__ __launch_bounds__(256, 1) void gemm_hmma_kernel(
    const float* __restrict__ A,     // x [M,256]
    const float* __restrict__ bias,
    const float* __restrict__ wq,
    const float* __restrict__ wk,
    int M)
{
    extern __shared__ char smem[];
    const uint32_t sb = smem_u32(smem);
    const int t    = threadIdx.x;
    const int wid  = t >> 5;
    const int lane = t & 31;
    const int wr   = wid >> 2;       // 0..1  (64-row band)
    const int wc   = wid & 3;        // 0..3  (64-col band)

    // epilogue vectors
    {
        float* wq_s = (float*)(smem + S_WQ);
        float* wk_s = (float*)(smem + S_WK);
        float* bi_s = (float*)(smem + S_BIAS);
        if (t < 256) { wq_s[t] = wq[t]; wk_s[t] = wk[t]; bi_s[t] = bias[t]; }
    }

    // A loader mapping: thread t owns row t>>1, 32 cols per chunk half
    const int lrow  = t >> 1;
    const int lhalf = t & 1;
    int arow = blockIdx.x * MTILE + lrow;
    if (arow >= M) arow = M - 1;                 // clamp; stores guarded
    const float4* arow4 = (const float4*)(A + (size_t)arow * 256);

    float acc[128];
    #pragma unroll
    for (int i = 0; i < 128; i++) acc[i] = 0.f;

    for (int c = 0; c < 4; c++) {
        // ---- load + split A chunk (rows 128, cols [c*64, c*64+64)) ----
        #pragma unroll
        for (int j = 0; j < 4; j++) {
            float4 a0 = arow4[c * 16 + lhalf * 8 + j * 2];
            float4 a1 = arow4[c * 16 + lhalf * 8 + j * 2 + 1];
            float f[8] = {a0.x, a0.y, a0.z, a0.w, a1.x, a1.y, a1.z, a1.w};
            __half2 hh[4], ll[4];
            #pragma unroll
            for (int p = 0; p < 4; p++) {
                __half h0 = __float2half_rn(f[2 * p]);
                __half h1 = __float2half_rn(f[2 * p + 1]);
                __half l0 = __float2half_rn(f[2 * p]     - __half2float(h0));
                __half l1 = __float2half_rn(f[2 * p + 1] - __half2float(h1));
                hh[p] = __halves2half2(h0, h1);
                ll[p] = __halves2half2(l0, l1);
            }
            uint32_t off = SWZ128((uint32_t)(lrow * 128 + (lhalf * 32 + j * 8) * 2));
            *(uint4*)(smem + S_AHI + off) = *(uint4*)hh;
            *(uint4*)(smem + S_ALO + off) = *(uint4*)ll;
        }
        // ---- copy B chunk (pre-swizzled) ----
        {
            const uint4* bh = (const uint4*)(g_Bhi + (size_t)c * 16384);
            const uint4* bl = (const uint4*)(g_Blo + (size_t)c * 16384);
            uint4* sh = (uint4*)(smem + S_BHI);
            uint4* sl = (uint4*)(smem + S_BLO);
            #pragma unroll
            for (int i = 0; i < 8; i++) {
                sh[t + i * 256] = bh[t + i * 256];
                sl[t + i * 256] = bl[t + i * 256];
            }
        }
        __syncthreads();

        // ---- compute: 4 k16 steps ----
        #pragma unroll
        for (int ks = 0; ks < 4; ks++) {
            uint32_t ah[16], al[16], bb[16];
            // A frags: mf 0..3, ldmatrix x4 (16 rows x 16 k)
            const uint32_t aoff =
                (uint32_t)((wr * 64 + (lane & 15)) * 128 + (ks * 16 + (lane >> 4) * 8) * 2);
            #pragma unroll
            for (int mf = 0; mf < 4; mf++) {
                uint32_t o = SWZ128(aoff + (uint32_t)(mf * 16 * 128));
                ldsm4(ah + mf * 4, sb + S_AHI + o);
                ldsm4(al + mf * 4, sb + S_ALO + o);
            }
            // B hi frags: nfrag pairs (x4 covers 2 n-frags)
            const uint32_t boff =
                (uint32_t)((wc * 64 + (lane & 7) + ((lane >> 4) & 1) * 8) * 128
                           + (ks * 16 + ((lane >> 3) & 1) * 8) * 2);
            #pragma unroll
            for (int np = 0; np < 4; np++) {
                uint32_t o = SWZ128(boff + (uint32_t)(np * 16 * 128));
                ldsm4(bb + np * 4, sb + S_BHI + o);
            }
            #pragma unroll
            for (int mf = 0; mf < 4; mf++)
                #pragma unroll
                for (int nf = 0; nf < 8; nf++) {
                    mma16816(acc + (mf * 8 + nf) * 4, ah + mf * 4, bb + nf * 2);
                    mma16816(acc + (mf * 8 + nf) * 4, al + mf * 4, bb + nf * 2);
                }
            // B lo frags into same regs, multiply with A hi
            #pragma unroll
            for (int np = 0; np < 4; np++) {
                uint32_t o = SWZ128(boff + (uint32_t)(np * 16 * 128));
                ldsm4(bb + np * 4, sb + S_BLO + o);
            }
            #pragma unroll
            for (int mf = 0; mf < 4; mf++)
                #pragma unroll
                for (int nf = 0; nf < 8; nf++)
                    mma16816(acc + (mf * 8 + nf) * 4, ah + mf * 4, bb + nf * 2);
        }
        __syncthreads();
    }

    // ---- epilogue ----
    const float* wq_s = (const float*)(smem + S_WQ);
    const float* wk_s = (const float*)(smem + S_WK);
    const float* bi_s = (const float*)(smem + S_BIAS);
    const int rowbase = blockIdx.x * MTILE + wr * 64 + (lane >> 2);

    float pq[8], pk[8];
    #pragma unroll
    for (int i = 0; i < 8; i++) { pq[i] = 0.f; pk[i] = 0.f; }

    #pragma unroll
    for (int nf = 0; nf < 8; nf++) {
        const int col = wc * 64 + nf * 8 + (lane & 3) * 2;
        const float bi0 = bi_s[col], bi1 = bi_s[col + 1];
        const float q0 = wq_s[col], q1 = wq_s[col + 1];
        const float k0 = wk_s[col], k1 = wk_s[col + 1];
        #pragma unroll
        for (int mf = 0; mf < 4; mf++) {
            const float* cc = acc + (mf * 8 + nf) * 4;
            float v0 = cc[0] + bi0, v1 = cc[1] + bi1;   // row rowbase+mf*16
            float v2 = cc[2] + bi0, v3 = cc[3] + bi1;   // row rowbase+mf*16+8
            int r0 = rowbase + mf * 16;
            if (r0 < M)
                *(__half2*)(g_hh + (size_t)r0 * 256 + col) = __floats2half2_rn(v0, v1);
            if (r0 + 8 < M)
                *(__half2*)(g_hh + (size_t)(r0 + 8) * 256 + col) = __floats2half2_rn(v2, v3);
            pq[mf * 2]     = fmaf(v0, q0, fmaf(v1, q1, pq[mf * 2]));
            pk[mf * 2]     = fmaf(v0, k0, fmaf(v1, k1, pk[mf * 2]));
            pq[mf * 2 + 1] = fmaf(v2, q0, fmaf(v3, q1, pq[mf * 2 + 1]));
            pk[mf * 2 + 1] = fmaf(v2, k0, fmaf(v3, k1, pk[mf * 2 + 1]));
        }
    }
    // quad reduction (lanes with same lane>>2 share rows)
    #pragma unroll
    for (int i = 0; i < 8; i++) {
        #pragma unroll
        for (int o = 1; o < 4; o <<= 1) {
            pq[i] += __shfl_xor_sync(0xFFFFFFFFu, pq[i], o);
            pk[i] += __shfl_xor_sync(0xFFFFFFFFu, pk[i], o);
        }
    }
    if ((lane & 3) == 0) {
        #pragma unroll
        for (int mf = 0; mf < 4; mf++) {
            int r0 = rowbase + mf * 16;
            if (r0 < M) {
                atomicAdd(&g_q[r0], pq[mf * 2]);
                atomicAdd(&g_k[r0], pk[mf * 2]);
            }
            if (r0 + 8 < M) {
                atomicAdd(&g_q[r0 + 8], pq[mf * 2 + 1]);
                atomicAdd(&g_k[r0 + 8], pk[mf * 2 + 1]);
            }
        }
    }
}

// ---------------------------------------------------------------------------
// K2: histogram of dst
// ---------------------------------------------------------------------------
__global__ __launch_bounds__(256) void hist_kernel(
    const int* __restrict__ dst, int E)
{
    int e = blockIdx.x * blockDim.x + threadIdx.x;
    if (e < E) atomicAdd(&g_cnt[dst[e]], 1);
}

// ---------------------------------------------------------------------------
// K3a/b/c: multi-block exclusive scan of g_cnt -> g_off (+cursor)
// ---------------------------------------------------------------------------
__global__ __launch_bounds__(SCAN_B) void partial_kernel(int n) {
    __shared__ int sh[SCAN_B];
    const int t = threadIdx.x;
    const int i = blockIdx.x * SCAN_B + t;
    sh[t] = (i < n) ? g_cnt[i] : 0;
    __syncthreads();
    #pragma unroll
    for (int o = SCAN_B / 2; o; o >>= 1) {
        if (t < o) sh[t] += sh[t + o];
        __syncthreads();
    }
    if (t == 0) g_bsum[blockIdx.x] = sh[0];
}

__global__ __launch_bounds__(128) void scanb_kernel(int nb) {
    __shared__ int sh[128];
    const int t = threadIdx.x;
    sh[t] = (t < nb) ? g_bsum[t] : 0;
    __syncthreads();
    #pragma unroll
    for (int o = 1; o < 128; o <<= 1) {
        int v = (t >= o) ? sh[t - o] : 0;
        __syncthreads();
        sh[t] += v;
        __syncthreads();
    }
    if (t < nb) g_bsum[t] = (t == 0) ? 0 : sh[t - 1];
}

__global__ __launch_bounds__(SCAN_B) void offsets_kernel(int n, int E) {
    __shared__ int sh[SCAN_B];
    const int t = threadIdx.x;
    const int i = blockIdx.x * SCAN_B + t;
    const int v = (i < n) ? g_cnt[i] : 0;
    sh[t] = v;
    __syncthreads();
    #pragma unroll
    for (int o = 1; o < SCAN_B; o <<= 1) {
        int u = (t >= o) ? sh[t - o] : 0;
        __syncthreads();
        sh[t] += u;
        __syncthreads();
    }
    if (i < n) {
        int excl = sh[t] - v + g_bsum[blockIdx.x];
        g_off[i] = excl;
        g_cnt[i] = excl;     // cursor for bucket scatter
        if (i == n - 1) g_off[n] = E;
    }
}

// ---------------------------------------------------------------------------
// K4: bucket-scatter src indices into dst-sorted order
// ---------------------------------------------------------------------------
__global__ __launch_bounds__(256) void bucket_kernel(
    const int* __restrict__ src, const int* __restrict__ dst, int E)
{
    int e = blockIdx.x * blockDim.x + threadIdx.x;
    if (e >= E) return;
    int pos = atomicAdd(&g_cnt[dst[e]], 1);
    g_src_sorted[pos] = src[e];
}

// ---------------------------------------------------------------------------
// K5: fused per-dst-segment softmax + weighted aggregation (one warp/node)
// ---------------------------------------------------------------------------
__global__ __launch_bounds__(256) void gat_segment_kernel(
    float* __restrict__ out, int n)
{
    int d    = (blockIdx.x * blockDim.x + threadIdx.x) >> 5;
    int lane = threadIdx.x & 31;
    if (d >= n) return;

    const int beg = g_off[d];
    const int end = g_off[d + 1];
    float4* orow = (float4*)(out + (size_t)d * F);

    if (beg == end) {
        float4 z = make_float4(0.f, 0.f, 0.f, 0.f);
        orow[lane * 2]     = z;
        orow[lane * 2 + 1] = z;
        return;
    }

    const float kd = g_k[d];

    float m = -INFINITY, s = 0.f;
    for (int i = beg + lane; i < end; i += 32) {
        float v = g_q[g_src_sorted[i]] + kd;
        float c = v > 0.f ? v : 0.2f * v;
        if (c > m) { s *= __expf(m - c); m = c; }
        s += __expf(c - m);
    }
    #pragma unroll
    for (int o = 16; o; o >>= 1) {
        float mo = __shfl_xor_sync(0xFFFFFFFFu, m, o);
        float so = __shfl_xor_sync(0xFFFFFFFFu, s, o);
        if (mo > m)       { s = s * __expf(m - mo) + so; m = mo; }
        else if (mo == m) { s += so; }
        else              { s += so * __expf(mo - m); }
    }
    const float inv_s = 1.0f / s;

    float a[8];
    #pragma unroll
    for (int j = 0; j < 8; j++) a[j] = 0.f;

    for (int i = beg; i < end; ++i) {
        int sidx = g_src_sorted[i];
        float v  = g_q[sidx] + kd;
        float c  = v > 0.f ? v : 0.2f * v;
        float w  = __expf(c - m) * inv_s;

        uint4 raw = *(const uint4*)(g_hh + (size_t)sidx * F + lane * 8);
        const __half2* hp = (const __half2*)&raw;
        #pragma unroll
        for (int j = 0; j < 4; j++) {
            float2 f = __half22float2(hp[j]);
            a[2 * j]     = fmaf(w, f.x, a[2 * j]);
            a[2 * j + 1] = fmaf(w, f.y, a[2 * j + 1]);
        }
    }
    orow[lane * 2]     = make_float4(a[0], a[1], a[2], a[3]);
    orow[lane * 2 + 1] = make_float4(a[4], a[5], a[6], a[7]);
}

// ---------------------------------------------------------------------------
extern "C" void kernel_launch(void* const* d_in, const int* in_sizes, int n_in,
                              void* d_out, int out_size)
{
    const float* x  = (const float*)d_in[0];
    const float* Wv = (const float*)d_in[1];
    const float* bv = (const float*)d_in[2];
    const float* wq = (const float*)d_in[3];
    const float* bq = (const float*)d_in[4];
    const float* wk = (const float*)d_in[5];
    const float* bk = (const float*)d_in[6];
    const int*   src = (const int*)d_in[7];
    const int*   dst = (const int*)d_in[8];

    const int M = in_sizes[0] / F;      // 100000
    const int E = in_sizes[7];          // 3200000
    const int nb = (M + SCAN_B - 1) / SCAN_B;

    cudaFuncSetAttribute(gemm_hmma_kernel,
                         cudaFuncAttributeMaxDynamicSharedMemorySize, S_TOTAL);

    init_kernel<<<(M + 255) / 256, 256>>>(bq, bk, M);
    convw_kernel<<<256, 256>>>(Wv);

    gemm_hmma_kernel<<<(M + MTILE - 1) / MTILE, 256, S_TOTAL>>>(
        x, bv, wq, wk, M);

    hist_kernel<<<(E + 255) / 256, 256>>>(dst, E);
    partial_kernel<<<nb, SCAN_B>>>(M);
    scanb_kernel<<<1, 128>>>(nb);
    offsets_kernel<<<nb, SCAN_B>>>(M, E);
    bucket_kernel<<<(E + 255) / 256, 256>>>(src, dst, E);

    gat_segment_kernel<<<(M * 32 + 255) / 256, 256>>>((float*)d_out, M);
}

// round 11
// speedup vs baseline: 3.1915x; 1.0263x over previous
#include <cuda_runtime.h>
#include <cuda_fp16.h>
#include <math.h>
#include <stdint.h>

#define NNODES 100000
#define NEDGES 3200000
#define F 256
#define SCAN_B 1024
#define MTILE 128

// Scratch (allocation-free contract: __device__ globals)
__device__ __half g_hh[(size_t)NNODES * F]; // 51.2 MB (L2-resident)
__device__ float g_q[NNODES];
__device__ float g_k[NNODES];
__device__ int   g_cnt[NNODES];             // histogram, then bucket cursor
__device__ int   g_off[NNODES + 1];         // CSR offsets by dst
__device__ int   g_src_sorted[NEDGES];      // src node per dst-sorted edge
__device__ int   g_bsum[128];               // per-block partial sums
// W (hi fp16 only; 2-product split) in [N=256][K] K-major, SW128-swizzled,
// 4 K-chunk tiles (chunk = 64 K-cols) of 16384 halves each.
__device__ __half g_Bhi[256 * 256];

// ---------------------------------------------------------------------------
// helpers
// ---------------------------------------------------------------------------
__device__ __forceinline__ uint32_t smem_u32(const void* p) {
    uint32_t a;
    asm("{ .reg .u64 t; cvta.to.shared.u64 t, %1; cvt.u32.u64 %0, t; }"
        : "=r"(a) : "l"(p));
    return a;
}
#define SWZ128(o) ((o) ^ (((o) >> 3) & 0x70))

__device__ __forceinline__ void ldsm4(uint32_t* r, uint32_t addr) {
    asm volatile("ldmatrix.sync.aligned.m8n8.x4.shared.b16 {%0,%1,%2,%3}, [%4];"
        : "=r"(r[0]), "=r"(r[1]), "=r"(r[2]), "=r"(r[3]) : "r"(addr));
}
__device__ __forceinline__ void mma16816(float* d, const uint32_t* a,
                                         const uint32_t* b) {
    asm volatile(
        "mma.sync.aligned.m16n8k16.row.col.f32.f16.f16.f32 "
        "{%0,%1,%2,%3}, {%4,%5,%6,%7}, {%8,%9}, {%0,%1,%2,%3};"
        : "+f"(d[0]), "+f"(d[1]), "+f"(d[2]), "+f"(d[3])
        : "r"(a[0]), "r"(a[1]), "r"(a[2]), "r"(a[3]), "r"(b[0]), "r"(b[1]));
}

// ---------------------------------------------------------------------------
// SMEM layout (dynamic)
// ---------------------------------------------------------------------------
#define S_WQ    0                       // 256 floats
#define S_WK    1024
#define S_BIAS  2048
#define S_AHI   4096                    // 128 x 64 fp16 = 16 KB (SW128)
#define S_ALO   (S_AHI + 16384)
#define S_BHI   (S_ALO + 16384)         // 256 x 64 fp16 = 32 KB (SW128)
#define S_TOTAL (S_BHI + 32768)         // 69632 B

// ---------------------------------------------------------------------------
// K0: zero histogram; init q/k accumulators with biases
// ---------------------------------------------------------------------------
__global__ void init_kernel(const float* __restrict__ bq,
                            const float* __restrict__ bk, int n) {
    int i = blockIdx.x * blockDim.x + threadIdx.x;
    if (i < n) { g_cnt[i] = 0; g_q[i] = bq[0]; g_k[i] = bk[0]; }
}

// ---------------------------------------------------------------------------
// K1: fused prep: blocks [0,256) convert W -> g_Bhi (SW128-swizzled chunks);
//     blocks [256,...) histogram dst with int4 vector loads (4 edges/thread).
// ---------------------------------------------------------------------------
__global__ __launch_bounds__(256) void prep_kernel(
    const float* __restrict__ W, const int* __restrict__ dst, int E)
{
    if (blockIdx.x < 256) {
        int idx = blockIdx.x * 256 + threadIdx.x;   // 0..65535
        int kk = idx & 63;          // K within chunk
        int n  = (idx >> 6) & 255;  // N row
        int c  = idx >> 14;         // chunk
        float v = W[(c * 64 + kk) * 256 + n];
        uint32_t off = SWZ128((uint32_t)(n * 128 + kk * 2));
        g_Bhi[(uint32_t)c * 16384u + (off >> 1)] = __float2half_rn(v);
    } else {
        int base = ((blockIdx.x - 256) * 256 + threadIdx.x) * 4;
        if (base + 3 < E) {
            int4 d = *(const int4*)(dst + base);
            atomicAdd(&g_cnt[d.x], 1);
            atomicAdd(&g_cnt[d.y], 1);
            atomicAdd(&g_cnt[d.z], 1);
            atomicAdd(&g_cnt[d.w], 1);
        } else {
            for (int e = base; e < E; e++) atomicAdd(&g_cnt[dst[e]], 1);
        }
    }
}

// ---------------------------------------------------------------------------
// K2a/b/c: multi-block exclusive scan of g_cnt -> g_off (+cursor)
// ---------------------------------------------------------------------------
__global__ __launch_bounds__(SCAN_B) void partial_kernel(int n) {
    __shared__ int sh[SCAN_B];
    const int t = threadIdx.x;
    const int i = blockIdx.x * SCAN_B + t;
    sh[t] = (i < n) ? g_cnt[i] : 0;
    __syncthreads();
    #pragma unroll
    for (int o = SCAN_B / 2; o; o >>= 1) {
        if (t < o) sh[t] += sh[t + o];
        __syncthreads();
    }
    if (t == 0) g_bsum[blockIdx.x] = sh[0];
}

__global__ __launch_bounds__(128) void scanb_kernel(int nb) {
    __shared__ int sh[128];
    const int t = threadIdx.x;
    sh[t] = (t < nb) ? g_bsum[t] : 0;
    __syncthreads();
    #pragma unroll
    for (int o = 1; o < 128; o <<= 1) {
        int v = (t >= o) ? sh[t - o] : 0;
        __syncthreads();
        sh[t] += v;
        __syncthreads();
    }
    if (t < nb) g_bsum[t] = (t == 0) ? 0 : sh[t - 1];
}

__global__ __launch_bounds__(SCAN_B) void offsets_kernel(int n, int E) {
    __shared__ int sh[SCAN_B];
    const int t = threadIdx.x;
    const int i = blockIdx.x * SCAN_B + t;
    const int v = (i < n) ? g_cnt[i] : 0;
    sh[t] = v;
    __syncthreads();
    #pragma unroll
    for (int o = 1; o < SCAN_B; o <<= 1) {
        int u = (t >= o) ? sh[t - o] : 0;
        __syncthreads();
        sh[t] += u;
        __syncthreads();
    }
    if (i < n) {
        int excl = sh[t] - v + g_bsum[blockIdx.x];
        g_off[i] = excl;
        g_cnt[i] = excl;     // cursor for bucket scatter
        if (i == n - 1) g_off[n] = E;
    }
}

// ---------------------------------------------------------------------------
// K3: HMMA GEMM (2-product split: x*Wh + xl*Wh, fp32 accum) + epilogue
//     (g_hh fp16, exact q/k partials) + APPENDED bucket-scatter slice.
// 256 threads = 8 warps, warp grid 2x4, warp tile 64x64.
// ---------------------------------------------------------------------------
__global__ __launch_bounds__(256, 1) void gemm_hmma_kernel(
    const float* __restrict__ A,     // x [M,256]
    const float* __restrict__ bias,
    const float* __restrict__ wq,
    const float* __restrict__ wk,
    const int* __restrict__ src,
    const int* __restrict__ dst,
    int M, int E)
{
    extern __shared__ char smem[];
    const uint32_t sb = smem_u32(smem);
    const int t    = threadIdx.x;
    const int wid  = t >> 5;
    const int lane = t & 31;
    const int wr   = wid >> 2;       // 0..1  (64-row band)
    const int wc   = wid & 3;        // 0..3  (64-col band)

    // epilogue vectors
    {
        float* wq_s = (float*)(smem + S_WQ);
        float* wk_s = (float*)(smem + S_WK);
        float* bi_s = (float*)(smem + S_BIAS);
        if (t < 256) { wq_s[t] = wq[t]; wk_s[t] = wk[t]; bi_s[t] = bias[t]; }
    }

    // A loader mapping: thread t owns row t>>1, 32 cols per chunk half
    const int lrow  = t >> 1;
    const int lhalf = t & 1;
    int arow = blockIdx.x * MTILE + lrow;
    if (arow >= M) arow = M - 1;                 // clamp; stores guarded
    const float4* arow4 = (const float4*)(A + (size_t)arow * 256);

    float acc[128];
    #pragma unroll
    for (int i = 0; i < 128; i++) acc[i] = 0.f;

    for (int c = 0; c < 4; c++) {
        // ---- load + split A chunk (rows 128, cols [c*64, c*64+64)) ----
        #pragma unroll
        for (int j = 0; j < 4; j++) {
            float4 a0 = arow4[c * 16 + lhalf * 8 + j * 2];
            float4 a1 = arow4[c * 16 + lhalf * 8 + j * 2 + 1];
            float f[8] = {a0.x, a0.y, a0.z, a0.w, a1.x, a1.y, a1.z, a1.w};
            __half2 hh[4], ll[4];
            #pragma unroll
            for (int p = 0; p < 4; p++) {
                __half h0 = __float2half_rn(f[2 * p]);
                __half h1 = __float2half_rn(f[2 * p + 1]);
                __half l0 = __float2half_rn(f[2 * p]     - __half2float(h0));
                __half l1 = __float2half_rn(f[2 * p + 1] - __half2float(h1));
                hh[p] = __halves2half2(h0, h1);
                ll[p] = __halves2half2(l0, l1);
            }
            uint32_t off = SWZ128((uint32_t)(lrow * 128 + (lhalf * 32 + j * 8) * 2));
            *(uint4*)(smem + S_AHI + off) = *(uint4*)hh;
            *(uint4*)(smem + S_ALO + off) = *(uint4*)ll;
        }
        // ---- copy B chunk (pre-swizzled hi only) ----
        {
            const uint4* bh = (const uint4*)(g_Bhi + (size_t)c * 16384);
            uint4* sh = (uint4*)(smem + S_BHI);
            #pragma unroll
            for (int i = 0; i < 8; i++)
                sh[t + i * 256] = bh[t + i * 256];
        }
        __syncthreads();

        // ---- compute: 4 k16 steps, 2 products (A hi + A lo vs B hi) ----
        #pragma unroll
        for (int ks = 0; ks < 4; ks++) {
            uint32_t ah[16], al[16], bb[16];
            const uint32_t aoff =
                (uint32_t)((wr * 64 + (lane & 15)) * 128 + (ks * 16 + (lane >> 4) * 8) * 2);
            #pragma unroll
            for (int mf = 0; mf < 4; mf++) {
                uint32_t o = SWZ128(aoff + (uint32_t)(mf * 16 * 128));
                ldsm4(ah + mf * 4, sb + S_AHI + o);
                ldsm4(al + mf * 4, sb + S_ALO + o);
            }
            const uint32_t boff =
                (uint32_t)((wc * 64 + (lane & 7) + ((lane >> 4) & 1) * 8) * 128
                           + (ks * 16 + ((lane >> 3) & 1) * 8) * 2);
            #pragma unroll
            for (int np = 0; np < 4; np++) {
                uint32_t o = SWZ128(boff + (uint32_t)(np * 16 * 128));
                ldsm4(bb + np * 4, sb + S_BHI + o);
            }
            #pragma unroll
            for (int mf = 0; mf < 4; mf++)
                #pragma unroll
                for (int nf = 0; nf < 8; nf++) {
                    mma16816(acc + (mf * 8 + nf) * 4, ah + mf * 4, bb + nf * 2);
                    mma16816(acc + (mf * 8 + nf) * 4, al + mf * 4, bb + nf * 2);
                }
        }
        __syncthreads();
    }

    // ---- epilogue ----
    const float* wq_s = (const float*)(smem + S_WQ);
    const float* wk_s = (const float*)(smem + S_WK);
    const float* bi_s = (const float*)(smem + S_BIAS);
    const int rowbase = blockIdx.x * MTILE + wr * 64 + (lane >> 2);

    float pq[8], pk[8];
    #pragma unroll
    for (int i = 0; i < 8; i++) { pq[i] = 0.f; pk[i] = 0.f; }

    #pragma unroll
    for (int nf = 0; nf < 8; nf++) {
        const int col = wc * 64 + nf * 8 + (lane & 3) * 2;
        const float bi0 = bi_s[col], bi1 = bi_s[col + 1];
        const float q0 = wq_s[col], q1 = wq_s[col + 1];
        const float k0 = wk_s[col], k1 = wk_s[col + 1];
        #pragma unroll
        for (int mf = 0; mf < 4; mf++) {
            const float* cc = acc + (mf * 8 + nf) * 4;
            float v0 = cc[0] + bi0, v1 = cc[1] + bi1;   // row rowbase+mf*16
            float v2 = cc[2] + bi0, v3 = cc[3] + bi1;   // row rowbase+mf*16+8
            int r0 = rowbase + mf * 16;
            if (r0 < M)
                *(__half2*)(g_hh + (size_t)r0 * 256 + col) = __floats2half2_rn(v0, v1);
            if (r0 + 8 < M)
                *(__half2*)(g_hh + (size_t)(r0 + 8) * 256 + col) = __floats2half2_rn(v2, v3);
            pq[mf * 2]     = fmaf(v0, q0, fmaf(v1, q1, pq[mf * 2]));
            pk[mf * 2]     = fmaf(v0, k0, fmaf(v1, k1, pk[mf * 2]));
            pq[mf * 2 + 1] = fmaf(v2, q0, fmaf(v3, q1, pq[mf * 2 + 1]));
            pk[mf * 2 + 1] = fmaf(v2, k0, fmaf(v3, k1, pk[mf * 2 + 1]));
        }
    }
    // quad reduction (lanes with same lane>>2 share rows)
    #pragma unroll
    for (int i = 0; i < 8; i++) {
        #pragma unroll
        for (int o = 1; o < 4; o <<= 1) {
            pq[i] += __shfl_xor_sync(0xFFFFFFFFu, pq[i], o);
            pk[i] += __shfl_xor_sync(0xFFFFFFFFu, pk[i], o);
        }
    }
    if ((lane & 3) == 0) {
        #pragma unroll
        for (int mf = 0; mf < 4; mf++) {
            int r0 = rowbase + mf * 16;
            if (r0 < M) {
                atomicAdd(&g_q[r0], pq[mf * 2]);
                atomicAdd(&g_k[r0], pk[mf * 2]);
            }
            if (r0 + 8 < M) {
                atomicAdd(&g_q[r0 + 8], pq[mf * 2 + 1]);
                atomicAdd(&g_k[r0 + 8], pk[mf * 2 + 1]);
            }
        }
    }

    // ---- appended bucket-scatter slice (offsets already computed) ----
    {
        const int nblk = gridDim.x;
        const int epb = (E + nblk - 1) / nblk;
        const int e0 = blockIdx.x * epb;
        int e1 = e0 + epb; if (e1 > E) e1 = E;
        for (int e = e0 + t; e < e1; e += 256) {
            int pos = atomicAdd(&g_cnt[dst[e]], 1);
            g_src_sorted[pos] = src[e];
        }
    }
}

// ---------------------------------------------------------------------------
// K4: fused per-dst-segment softmax + weighted aggregation (one warp/node)
// ---------------------------------------------------------------------------
__global__ __launch_bounds__(256) void gat_segment_kernel(
    float* __restrict__ out, int n)
{
    int d    = (blockIdx.x * blockDim.x + threadIdx.x) >> 5;
    int lane = threadIdx.x & 31;
    if (d >= n) return;

    const int beg = g_off[d];
    const int end = g_off[d + 1];
    float4* orow = (float4*)(out + (size_t)d * F);

    if (beg == end) {
        float4 z = make_float4(0.f, 0.f, 0.f, 0.f);
        orow[lane * 2]     = z;
        orow[lane * 2 + 1] = z;
        return;
    }

    const float kd = g_k[d];

    float m = -INFINITY, s = 0.f;
    for (int i = beg + lane; i < end; i += 32) {
        float v = g_q[g_src_sorted[i]] + kd;
        float c = v > 0.f ? v : 0.2f * v;
        if (c > m) { s *= __expf(m - c); m = c; }
        s += __expf(c - m);
    }
    #pragma unroll
    for (int o = 16; o; o >>= 1) {
        float mo = __shfl_xor_sync(0xFFFFFFFFu, m, o);
        float so = __shfl_xor_sync(0xFFFFFFFFu, s, o);
        if (mo > m)       { s = s * __expf(m - mo) + so; m = mo; }
        else if (mo == m) { s += so; }
        else              { s += so * __expf(mo - m); }
    }
    const float inv_s = 1.0f / s;

    float a[8];
    #pragma unroll
    for (int j = 0; j < 8; j++) a[j] = 0.f;

    for (int i = beg; i < end; ++i) {
        int sidx = g_src_sorted[i];
        float v  = g_q[sidx] + kd;
        float c  = v > 0.f ? v : 0.2f * v;
        float w  = __expf(c - m) * inv_s;

        uint4 raw = *(const uint4*)(g_hh + (size_t)sidx * F + lane * 8);
        const __half2* hp = (const __half2*)&raw;
        #pragma unroll
        for (int j = 0; j < 4; j++) {
            float2 f = __half22float2(hp[j]);
            a[2 * j]     = fmaf(w, f.x, a[2 * j]);
            a[2 * j + 1] = fmaf(w, f.y, a[2 * j + 1]);
        }
    }
    orow[lane * 2]     = make_float4(a[0], a[1], a[2], a[3]);
    orow[lane * 2 + 1] = make_float4(a[4], a[5], a[6], a[7]);
}

// ---------------------------------------------------------------------------
extern "C" void kernel_launch(void* const* d_in, const int* in_sizes, int n_in,
                              void* d_out, int out_size)
{
    const float* x  = (const float*)d_in[0];
    const float* Wv = (const float*)d_in[1];
    const float* bv = (const float*)d_in[2];
    const float* wq = (const float*)d_in[3];
    const float* bq = (const float*)d_in[4];
    const float* wk = (const float*)d_in[5];
    const float* bk = (const float*)d_in[6];
    const int*   src = (const int*)d_in[7];
    const int*   dst = (const int*)d_in[8];

    const int M = in_sizes[0] / F;      // 100000
    const int E = in_sizes[7];          // 3200000
    const int nb = (M + SCAN_B - 1) / SCAN_B;
    const int hist_blocks = (E / 4 + 255) / 256;     // int4 hist

    cudaFuncSetAttribute(gemm_hmma_kernel,
                         cudaFuncAttributeMaxDynamicSharedMemorySize, S_TOTAL);

    init_kernel<<<(M + 255) / 256, 256>>>(bq, bk, M);
    prep_kernel<<<256 + hist_blocks, 256>>>(Wv, dst, E);
    partial_kernel<<<nb, SCAN_B>>>(M);
    scanb_kernel<<<1, 128>>>(nb);
    offsets_kernel<<<nb, SCAN_B>>>(M, E);

    gemm_hmma_kernel<<<(M + MTILE - 1) / MTILE, 256, S_TOTAL>>>(
        x, bv, wq, wk, src, dst, M, E);

    gat_segment_kernel<<<(M * 32 + 255) / 256, 256>>>((float*)d_out, M);
}

// round 12
// speedup vs baseline: 3.3623x; 1.0535x over previous
#include <cuda_runtime.h>
#include <cuda_fp16.h>
#include <math.h>
#include <stdint.h>

#define NNODES 100000
#define NEDGES 3200000
#define F 256
#define SCAN_B 1024
#define MTILE 128

// Scratch (allocation-free contract: __device__ globals)
__device__ __half g_hh[(size_t)NNODES * F]; // 51.2 MB (L2-resident)
__device__ float g_q[NNODES];
__device__ float g_k[NNODES];
__device__ int   g_cnt[NNODES];             // histogram, then bucket cursor
__device__ int   g_off[NNODES + 1];         // CSR offsets by dst
__device__ int   g_src_sorted[NEDGES];      // src node per dst-sorted edge
__device__ int   g_bsum[128];               // per-block partial sums
// W (hi fp16 only; 2-product split) in [N=256][K] K-major, SW128-swizzled,
// 4 K-chunk tiles (chunk = 64 K-cols) of 16384 halves each.
__device__ __half g_Bhi[256 * 256];

// ---------------------------------------------------------------------------
// helpers
// ---------------------------------------------------------------------------
__device__ __forceinline__ uint32_t smem_u32(const void* p) {
    uint32_t a;
    asm("{ .reg .u64 t; cvta.to.shared.u64 t, %1; cvt.u32.u64 %0, t; }"
        : "=r"(a) : "l"(p));
    return a;
}
#define SWZ128(o) ((o) ^ (((o) >> 3) & 0x70))

__device__ __forceinline__ void ldsm4(uint32_t* r, uint32_t addr) {
    asm volatile("ldmatrix.sync.aligned.m8n8.x4.shared.b16 {%0,%1,%2,%3}, [%4];"
        : "=r"(r[0]), "=r"(r[1]), "=r"(r[2]), "=r"(r[3]) : "r"(addr));
}
__device__ __forceinline__ void mma16816(float* d, const uint32_t* a,
                                         const uint32_t* b) {
    asm volatile(
        "mma.sync.aligned.m16n8k16.row.col.f32.f16.f16.f32 "
        "{%0,%1,%2,%3}, {%4,%5,%6,%7}, {%8,%9}, {%0,%1,%2,%3};"
        : "+f"(d[0]), "+f"(d[1]), "+f"(d[2]), "+f"(d[3])
        : "r"(a[0]), "r"(a[1]), "r"(a[2]), "r"(a[3]), "r"(b[0]), "r"(b[1]));
}

// ---------------------------------------------------------------------------
// SMEM layout (dynamic)
// ---------------------------------------------------------------------------
#define S_WQ    0                       // 256 floats
#define S_WK    1024
#define S_BIAS  2048
#define S_AHI   4096                    // 128 x 64 fp16 = 16 KB (SW128)
#define S_ALO   (S_AHI + 16384)
#define S_BHI   (S_ALO + 16384)         // 256 x 64 fp16 = 32 KB (SW128)
#define S_TOTAL (S_BHI + 32768)         // 69632 B

// ---------------------------------------------------------------------------
// K0: zero histogram; init q/k accumulators with biases
// ---------------------------------------------------------------------------
__global__ void init_kernel(const float* __restrict__ bq,
                            const float* __restrict__ bk, int n) {
    int i = blockIdx.x * blockDim.x + threadIdx.x;
    if (i < n) { g_cnt[i] = 0; g_q[i] = bq[0]; g_k[i] = bk[0]; }
}

// ---------------------------------------------------------------------------
// K1: fused prep: blocks [0,256) convert W -> g_Bhi (SW128-swizzled chunks);
//     blocks [256,...) histogram dst with int4 vector loads (4 edges/thread).
// ---------------------------------------------------------------------------
__global__ __launch_bounds__(256) void prep_kernel(
    const float* __restrict__ W, const int* __restrict__ dst, int E)
{
    if (blockIdx.x < 256) {
        int idx = blockIdx.x * 256 + threadIdx.x;   // 0..65535
        int kk = idx & 63;          // K within chunk
        int n  = (idx >> 6) & 255;  // N row
        int c  = idx >> 14;         // chunk
        float v = W[(c * 64 + kk) * 256 + n];
        uint32_t off = SWZ128((uint32_t)(n * 128 + kk * 2));
        g_Bhi[(uint32_t)c * 16384u + (off >> 1)] = __float2half_rn(v);
    } else {
        int base = ((blockIdx.x - 256) * 256 + threadIdx.x) * 4;
        if (base + 3 < E) {
            int4 d = *(const int4*)(dst + base);
            atomicAdd(&g_cnt[d.x], 1);
            atomicAdd(&g_cnt[d.y], 1);
            atomicAdd(&g_cnt[d.z], 1);
            atomicAdd(&g_cnt[d.w], 1);
        } else {
            for (int e = base; e < E; e++) atomicAdd(&g_cnt[dst[e]], 1);
        }
    }
}

// ---------------------------------------------------------------------------
// K2a/b/c: multi-block exclusive scan of g_cnt -> g_off (+cursor)
// ---------------------------------------------------------------------------
__global__ __launch_bounds__(SCAN_B) void partial_kernel(int n) {
    __shared__ int sh[SCAN_B];
    const int t = threadIdx.x;
    const int i = blockIdx.x * SCAN_B + t;
    sh[t] = (i < n) ? g_cnt[i] : 0;
    __syncthreads();
    #pragma unroll
    for (int o = SCAN_B / 2; o; o >>= 1) {
        if (t < o) sh[t] += sh[t + o];
        __syncthreads();
    }
    if (t == 0) g_bsum[blockIdx.x] = sh[0];
}

__global__ __launch_bounds__(128) void scanb_kernel(int nb) {
    __shared__ int sh[128];
    const int t = threadIdx.x;
    sh[t] = (t < nb) ? g_bsum[t] : 0;
    __syncthreads();
    #pragma unroll
    for (int o = 1; o < 128; o <<= 1) {
        int v = (t >= o) ? sh[t - o] : 0;
        __syncthreads();
        sh[t] += v;
        __syncthreads();
    }
    if (t < nb) g_bsum[t] = (t == 0) ? 0 : sh[t - 1];
}

__global__ __launch_bounds__(SCAN_B) void offsets_kernel(int n, int E) {
    __shared__ int sh[SCAN_B];
    const int t = threadIdx.x;
    const int i = blockIdx.x * SCAN_B + t;
    const int v = (i < n) ? g_cnt[i] : 0;
    sh[t] = v;
    __syncthreads();
    #pragma unroll
    for (int o = 1; o < SCAN_B; o <<= 1) {
        int u = (t >= o) ? sh[t - o] : 0;
        __syncthreads();
        sh[t] += u;
        __syncthreads();
    }
    if (i < n) {
        int excl = sh[t] - v + g_bsum[blockIdx.x];
        g_off[i] = excl;
        g_cnt[i] = excl;     // cursor for bucket scatter
        if (i == n - 1) g_off[n] = E;
    }
}

// ---------------------------------------------------------------------------
// K3: HMMA GEMM (2-product split: x*Wh + xl*Wh, fp32 accum) + epilogue
//     (g_hh fp16, exact q/k partials) + APPENDED bucket-scatter slice.
// 256 threads = 8 warps, warp grid 2x4, warp tile 64x64.
// ---------------------------------------------------------------------------
__global__ __launch_bounds__(256, 1) void gemm_hmma_kernel(
    const float* __restrict__ A,     // x [M,256]
    const float* __restrict__ bias,
    const float* __restrict__ wq,
    const float* __restrict__ wk,
    const int* __restrict__ src,
    const int* __restrict__ dst,
    int M, int E)
{
    extern __shared__ char smem[];
    const uint32_t sb = smem_u32(smem);
    const int t    = threadIdx.x;
    const int wid  = t >> 5;
    const int lane = t & 31;
    const int wr   = wid >> 2;       // 0..1  (64-row band)
    const int wc   = wid & 3;        // 0..3  (64-col band)

    // epilogue vectors
    {
        float* wq_s = (float*)(smem + S_WQ);
        float* wk_s = (float*)(smem + S_WK);
        float* bi_s = (float*)(smem + S_BIAS);
        if (t < 256) { wq_s[t] = wq[t]; wk_s[t] = wk[t]; bi_s[t] = bias[t]; }
    }

    // A loader mapping: thread t owns row t>>1, 32 cols per chunk half
    const int lrow  = t >> 1;
    const int lhalf = t & 1;
    int arow = blockIdx.x * MTILE + lrow;
    if (arow >= M) arow = M - 1;                 // clamp; stores guarded
    const float4* arow4 = (const float4*)(A + (size_t)arow * 256);

    float acc[128];
    #pragma unroll
    for (int i = 0; i < 128; i++) acc[i] = 0.f;

    for (int c = 0; c < 4; c++) {
        // ---- load + split A chunk (rows 128, cols [c*64, c*64+64)) ----
        #pragma unroll
        for (int j = 0; j < 4; j++) {
            float4 a0 = arow4[c * 16 + lhalf * 8 + j * 2];
            float4 a1 = arow4[c * 16 + lhalf * 8 + j * 2 + 1];
            float f[8] = {a0.x, a0.y, a0.z, a0.w, a1.x, a1.y, a1.z, a1.w};
            __half2 hh[4], ll[4];
            #pragma unroll
            for (int p = 0; p < 4; p++) {
                __half h0 = __float2half_rn(f[2 * p]);
                __half h1 = __float2half_rn(f[2 * p + 1]);
                __half l0 = __float2half_rn(f[2 * p]     - __half2float(h0));
                __half l1 = __float2half_rn(f[2 * p + 1] - __half2float(h1));
                hh[p] = __halves2half2(h0, h1);
                ll[p] = __halves2half2(l0, l1);
            }
            uint32_t off = SWZ128((uint32_t)(lrow * 128 + (lhalf * 32 + j * 8) * 2));
            *(uint4*)(smem + S_AHI + off) = *(uint4*)hh;
            *(uint4*)(smem + S_ALO + off) = *(uint4*)ll;
        }
        // ---- copy B chunk (pre-swizzled hi only) ----
        {
            const uint4* bh = (const uint4*)(g_Bhi + (size_t)c * 16384);
            uint4* sh = (uint4*)(smem + S_BHI);
            #pragma unroll
            for (int i = 0; i < 8; i++)
                sh[t + i * 256] = bh[t + i * 256];
        }
        __syncthreads();

        // ---- compute: 4 k16 steps, 2 products (A hi + A lo vs B hi) ----
        #pragma unroll
        for (int ks = 0; ks < 4; ks++) {
            uint32_t ah[16], al[16], bb[16];
            const uint32_t aoff =
                (uint32_t)((wr * 64 + (lane & 15)) * 128 + (ks * 16 + (lane >> 4) * 8) * 2);
            #pragma unroll
            for (int mf = 0; mf < 4; mf++) {
                uint32_t o = SWZ128(aoff + (uint32_t)(mf * 16 * 128));
                ldsm4(ah + mf * 4, sb + S_AHI + o);
                ldsm4(al + mf * 4, sb + S_ALO + o);
            }
            const uint32_t boff =
                (uint32_t)((wc * 64 + (lane & 7) + ((lane >> 4) & 1) * 8) * 128
                           + (ks * 16 + ((lane >> 3) & 1) * 8) * 2);
            #pragma unroll
            for (int np = 0; np < 4; np++) {
                uint32_t o = SWZ128(boff + (uint32_t)(np * 16 * 128));
                ldsm4(bb + np * 4, sb + S_BHI + o);
            }
            #pragma unroll
            for (int mf = 0; mf < 4; mf++)
                #pragma unroll
                for (int nf = 0; nf < 8; nf++) {
                    mma16816(acc + (mf * 8 + nf) * 4, ah + mf * 4, bb + nf * 2);
                    mma16816(acc + (mf * 8 + nf) * 4, al + mf * 4, bb + nf * 2);
                }
        }
        __syncthreads();
    }

    // ---- epilogue ----
    const float* wq_s = (const float*)(smem + S_WQ);
    const float* wk_s = (const float*)(smem + S_WK);
    const float* bi_s = (const float*)(smem + S_BIAS);
    const int rowbase = blockIdx.x * MTILE + wr * 64 + (lane >> 2);

    float pq[8], pk[8];
    #pragma unroll
    for (int i = 0; i < 8; i++) { pq[i] = 0.f; pk[i] = 0.f; }

    #pragma unroll
    for (int nf = 0; nf < 8; nf++) {
        const int col = wc * 64 + nf * 8 + (lane & 3) * 2;
        const float bi0 = bi_s[col], bi1 = bi_s[col + 1];
        const float q0 = wq_s[col], q1 = wq_s[col + 1];
        const float k0 = wk_s[col], k1 = wk_s[col + 1];
        #pragma unroll
        for (int mf = 0; mf < 4; mf++) {
            const float* cc = acc + (mf * 8 + nf) * 4;
            float v0 = cc[0] + bi0, v1 = cc[1] + bi1;   // row rowbase+mf*16
            float v2 = cc[2] + bi0, v3 = cc[3] + bi1;   // row rowbase+mf*16+8
            int r0 = rowbase + mf * 16;
            if (r0 < M)
                *(__half2*)(g_hh + (size_t)r0 * 256 + col) = __floats2half2_rn(v0, v1);
            if (r0 + 8 < M)
                *(__half2*)(g_hh + (size_t)(r0 + 8) * 256 + col) = __floats2half2_rn(v2, v3);
            pq[mf * 2]     = fmaf(v0, q0, fmaf(v1, q1, pq[mf * 2]));
            pk[mf * 2]     = fmaf(v0, k0, fmaf(v1, k1, pk[mf * 2]));
            pq[mf * 2 + 1] = fmaf(v2, q0, fmaf(v3, q1, pq[mf * 2 + 1]));
            pk[mf * 2 + 1] = fmaf(v2, k0, fmaf(v3, k1, pk[mf * 2 + 1]));
        }
    }
    // quad reduction (lanes with same lane>>2 share rows)
    #pragma unroll
    for (int i = 0; i < 8; i++) {
        #pragma unroll
        for (int o = 1; o < 4; o <<= 1) {
            pq[i] += __shfl_xor_sync(0xFFFFFFFFu, pq[i], o);
            pk[i] += __shfl_xor_sync(0xFFFFFFFFu, pk[i], o);
        }
    }
    if ((lane & 3) == 0) {
        #pragma unroll
        for (int mf = 0; mf < 4; mf++) {
            int r0 = rowbase + mf * 16;
            if (r0 < M) {
                atomicAdd(&g_q[r0], pq[mf * 2]);
                atomicAdd(&g_k[r0], pk[mf * 2]);
            }
            if (r0 + 8 < M) {
                atomicAdd(&g_q[r0 + 8], pq[mf * 2 + 1]);
                atomicAdd(&g_k[r0 + 8], pk[mf * 2 + 1]);
            }
        }
    }

    // ---- appended bucket-scatter slice (offsets already computed) ----
    {
        const int nblk = gridDim.x;
        const int epb = (E + nblk - 1) / nblk;
        const int e0 = blockIdx.x * epb;
        int e1 = e0 + epb; if (e1 > E) e1 = E;
        for (int e = e0 + t; e < e1; e += 256) {
            int pos = atomicAdd(&g_cnt[dst[e]], 1);
            g_src_sorted[pos] = src[e];
        }
    }
}

// ---------------------------------------------------------------------------
// K4: fused per-dst-segment softmax + weighted aggregation (one warp/node).
// Pass 2 software-pipelined x4: batch index loads + 4 independent row
// gathers in flight to raise MLP (latency-bound fix).
// ---------------------------------------------------------------------------
__global__ __launch_bounds__(256) void gat_segment_kernel(
    float* __restrict__ out, int n)
{
    int d    = (blockIdx.x * blockDim.x + threadIdx.x) >> 5;
    int lane = threadIdx.x & 31;
    if (d >= n) return;

    const int beg = g_off[d];
    const int end = g_off[d + 1];
    float4* orow = (float4*)(out + (size_t)d * F);

    if (beg == end) {
        float4 z = make_float4(0.f, 0.f, 0.f, 0.f);
        orow[lane * 2]     = z;
        orow[lane * 2 + 1] = z;
        return;
    }

    const float kd = g_k[d];

    // Pass 1: online softmax statistics, lanes stride over segment
    float m = -INFINITY, s = 0.f;
    for (int i = beg + lane; i < end; i += 32) {
        float v = g_q[g_src_sorted[i]] + kd;
        float c = v > 0.f ? v : 0.2f * v;
        if (c > m) { s *= __expf(m - c); m = c; }
        s += __expf(c - m);
    }
    #pragma unroll
    for (int o = 16; o; o >>= 1) {
        float mo = __shfl_xor_sync(0xFFFFFFFFu, m, o);
        float so = __shfl_xor_sync(0xFFFFFFFFu, s, o);
        if (mo > m)       { s = s * __expf(m - mo) + so; m = mo; }
        else if (mo == m) { s += so; }
        else              { s += so * __expf(mo - m); }
    }
    const float inv_s = 1.0f / s;

    // Pass 2: 4x software-pipelined over edges; lanes cover the feature dim
    float a[8];
    #pragma unroll
    for (int j = 0; j < 8; j++) a[j] = 0.f;

    const __half* hbase = g_hh + (size_t)lane * 8;

    int i = beg;
    for (; i + 4 <= end; i += 4) {
        // batch 1: indices (sequential, L1-resident)
        int s0 = g_src_sorted[i + 0];
        int s1 = g_src_sorted[i + 1];
        int s2 = g_src_sorted[i + 2];
        int s3 = g_src_sorted[i + 3];
        // batch 2: q gathers (independent)
        float q0 = g_q[s0], q1 = g_q[s1], q2 = g_q[s2], q3 = g_q[s3];
        // batch 3: 4 independent 16B row gathers in flight
        uint4 r0 = *(const uint4*)(hbase + (size_t)s0 * F);
        uint4 r1 = *(const uint4*)(hbase + (size_t)s1 * F);
        uint4 r2 = *(const uint4*)(hbase + (size_t)s2 * F);
        uint4 r3 = *(const uint4*)(hbase + (size_t)s3 * F);
        // weights
        float v0 = q0 + kd, v1 = q1 + kd, v2 = q2 + kd, v3 = q3 + kd;
        float c0 = v0 > 0.f ? v0 : 0.2f * v0;
        float c1 = v1 > 0.f ? v1 : 0.2f * v1;
        float c2 = v2 > 0.f ? v2 : 0.2f * v2;
        float c3 = v3 > 0.f ? v3 : 0.2f * v3;
        float w0 = __expf(c0 - m) * inv_s;
        float w1 = __expf(c1 - m) * inv_s;
        float w2 = __expf(c2 - m) * inv_s;
        float w3 = __expf(c3 - m) * inv_s;
        // accumulate (same per-accumulator order as scalar loop)
        const __half2* p0 = (const __half2*)&r0;
        const __half2* p1 = (const __half2*)&r1;
        const __half2* p2 = (const __half2*)&r2;
        const __half2* p3 = (const __half2*)&r3;
        #pragma unroll
        for (int j = 0; j < 4; j++) {
            float2 f0 = __half22float2(p0[j]);
            float2 f1 = __half22float2(p1[j]);
            float2 f2 = __half22float2(p2[j]);
            float2 f3 = __half22float2(p3[j]);
            a[2 * j]     = fmaf(w0, f0.x, a[2 * j]);
            a[2 * j + 1] = fmaf(w0, f0.y, a[2 * j + 1]);
            a[2 * j]     = fmaf(w1, f1.x, a[2 * j]);
            a[2 * j + 1] = fmaf(w1, f1.y, a[2 * j + 1]);
            a[2 * j]     = fmaf(w2, f2.x, a[2 * j]);
            a[2 * j + 1] = fmaf(w2, f2.y, a[2 * j + 1]);
            a[2 * j]     = fmaf(w3, f3.x, a[2 * j]);
            a[2 * j + 1] = fmaf(w3, f3.y, a[2 * j + 1]);
        }
    }
    // tail
    for (; i < end; ++i) {
        int sidx = g_src_sorted[i];
        float v  = g_q[sidx] + kd;
        float c  = v > 0.f ? v : 0.2f * v;
        float w  = __expf(c - m) * inv_s;
        uint4 raw = *(const uint4*)(hbase + (size_t)sidx * F);
        const __half2* hp = (const __half2*)&raw;
        #pragma unroll
        for (int j = 0; j < 4; j++) {
            float2 f = __half22float2(hp[j]);
            a[2 * j]     = fmaf(w, f.x, a[2 * j]);
            a[2 * j + 1] = fmaf(w, f.y, a[2 * j + 1]);
        }
    }
    orow[lane * 2]     = make_float4(a[0], a[1], a[2], a[3]);
    orow[lane * 2 + 1] = make_float4(a[4], a[5], a[6], a[7]);
}

// ---------------------------------------------------------------------------
extern "C" void kernel_launch(void* const* d_in, const int* in_sizes, int n_in,
                              void* d_out, int out_size)
{
    const float* x  = (const float*)d_in[0];
    const float* Wv = (const float*)d_in[1];
    const float* bv = (const float*)d_in[2];
    const float* wq = (const float*)d_in[3];
    const float* bq = (const float*)d_in[4];
    const float* wk = (const float*)d_in[5];
    const float* bk = (const float*)d_in[6];
    const int*   src = (const int*)d_in[7];
    const int*   dst = (const int*)d_in[8];

    const int M = in_sizes[0] / F;      // 100000
    const int E = in_sizes[7];          // 3200000
    const int nb = (M + SCAN_B - 1) / SCAN_B;
    const int hist_blocks = (E / 4 + 255) / 256;     // int4 hist

    cudaFuncSetAttribute(gemm_hmma_kernel,
                         cudaFuncAttributeMaxDynamicSharedMemorySize, S_TOTAL);

    init_kernel<<<(M + 255) / 256, 256>>>(bq, bk, M);
    prep_kernel<<<256 + hist_blocks, 256>>>(Wv, dst, E);
    partial_kernel<<<nb, SCAN_B>>>(M);
    scanb_kernel<<<1, 128>>>(nb);
    offsets_kernel<<<nb, SCAN_B>>>(M, E);

    gemm_hmma_kernel<<<(M + MTILE - 1) / MTILE, 256, S_TOTAL>>>(
        x, bv, wq, wk, src, dst, M, E);

    gat_segment_kernel<<<(M * 32 + 255) / 256, 256>>>((float*)d_out, M);
}